// round 11
// baseline (speedup 1.0000x reference)
#include <cuda_runtime.h>
#include <cuda_bf16.h>
#include <cstdint>

#define SEQ    4096
#define HIDDEN 2048
#define NH     16
#define NKV    2
#define HD     256
#define RHALF  32
#define GQ     (NH / NKV)

// ---------------------------------------------------------------------------
// Scratch (device globals — no allocations allowed)
// ---------------------------------------------------------------------------
__device__ float g_q[(size_t)SEQ * NH * HD];       // 64 MB
__device__ float g_k[(size_t)SEQ * NKV * HD];      // 8 MB
__device__ float g_v[(size_t)SEQ * NKV * HD];      // 8 MB

// bf16 hi/lo split operands
__device__ __nv_bfloat16 g_hsh[(size_t)SEQ * HIDDEN];
__device__ __nv_bfloat16 g_hsl[(size_t)SEQ * HIDDEN];
__device__ __nv_bfloat16 g_qh[(size_t)SEQ * NH * HD];
__device__ __nv_bfloat16 g_ql[(size_t)SEQ * NH * HD];
__device__ __nv_bfloat16 g_kh[(size_t)SEQ * NKV * HD];
__device__ __nv_bfloat16 g_kl[(size_t)SEQ * NKV * HD];
__device__ __nv_bfloat16 g_vth[(size_t)NKV * HD * SEQ];   // [kvh][d][s]
__device__ __nv_bfloat16 g_vtl[(size_t)NKV * HD * SEQ];
__device__ __nv_bfloat16 g_ctxh[(size_t)SEQ * NH * HD];   // attention out (hi/lo)
__device__ __nv_bfloat16 g_ctxl[(size_t)SEQ * NH * HD];
__device__ __nv_bfloat16 g_wqth[(size_t)(NH * HD) * HIDDEN];
__device__ __nv_bfloat16 g_wqtl[(size_t)(NH * HD) * HIDDEN];
__device__ __nv_bfloat16 g_wkth[(size_t)(NKV * HD) * HIDDEN];
__device__ __nv_bfloat16 g_wktl[(size_t)(NKV * HD) * HIDDEN];
__device__ __nv_bfloat16 g_wvth[(size_t)(NKV * HD) * HIDDEN];
__device__ __nv_bfloat16 g_wvtl[(size_t)(NKV * HD) * HIDDEN];
__device__ __nv_bfloat16 g_woth[(size_t)HIDDEN * (NH * HD)];
__device__ __nv_bfloat16 g_wotl[(size_t)HIDDEN * (NH * HD)];

// ---------------------------------------------------------------------------
// mma.sync m16n8k16 bf16 -> fp32 (baseline-PTX tensor path; verified R9/R10)
// ---------------------------------------------------------------------------
__device__ __forceinline__ void mma16816(float c[4],
                                         uint32_t a0, uint32_t a1, uint32_t a2, uint32_t a3,
                                         uint32_t b0, uint32_t b1) {
    asm volatile(
        "mma.sync.aligned.m16n8k16.row.col.f32.bf16.bf16.f32 "
        "{%0,%1,%2,%3}, {%4,%5,%6,%7}, {%8,%9}, {%0,%1,%2,%3};"
        : "+f"(c[0]), "+f"(c[1]), "+f"(c[2]), "+f"(c[3])
        : "r"(a0), "r"(a1), "r"(a2), "r"(a3), "r"(b0), "r"(b1));
}

__device__ __forceinline__ uint32_t pack2bf16(float a, float b) {
    __nv_bfloat162 t = __floats2bfloat162_rn(a, b);
    return *(uint32_t*)&t;
}

__device__ __forceinline__ uint32_t smem_u32(const void* p) {
    uint32_t a;
    asm("{ .reg .u64 t; cvta.to.shared.u64 t, %1; cvt.u32.u64 %0, t; }"
        : "=r"(a) : "l"(p));
    return a;
}

__device__ __forceinline__ void cp16(uint32_t dst, const void* src) {
    asm volatile("cp.async.cg.shared.global [%0], [%1], 16;" :: "r"(dst), "l"(src));
}
#define CP_COMMIT() asm volatile("cp.async.commit_group;" ::: "memory")
#define CP_WAIT(n)  asm volatile("cp.async.wait_group %0;" :: "n"(n) : "memory")

// ---------------------------------------------------------------------------
// Prep kernels
// ---------------------------------------------------------------------------
__global__ void __launch_bounds__(256) split_hi_lo(const float* __restrict__ x,
                                                   __nv_bfloat16* __restrict__ hi,
                                                   __nv_bfloat16* __restrict__ lo) {
    int i = blockIdx.x * 256 + threadIdx.x;
    float4 v = ((const float4*)x)[i];
    __nv_bfloat16 h0 = __float2bfloat16(v.x), h1 = __float2bfloat16(v.y);
    __nv_bfloat16 h2 = __float2bfloat16(v.z), h3 = __float2bfloat16(v.w);
    uint2 hp, lp;
    hp.x = pack2bf16(v.x, v.y); hp.y = pack2bf16(v.z, v.w);
    lp.x = pack2bf16(v.x - __bfloat162float(h0), v.y - __bfloat162float(h1));
    lp.y = pack2bf16(v.z - __bfloat162float(h2), v.w - __bfloat162float(h3));
    ((uint2*)hi)[i] = hp;
    ((uint2*)lo)[i] = lp;
}

// W [K][N] fp32 -> WT_hi/lo [N][K] bf16 (32x32 smem tile transpose)
__global__ void __launch_bounds__(256) transpose_split(const float* __restrict__ w,
                                                       __nv_bfloat16* __restrict__ th,
                                                       __nv_bfloat16* __restrict__ tl,
                                                       int K, int N) {
    __shared__ float tile[32][33];
    int n0 = blockIdx.x * 32, k0 = blockIdx.y * 32;
    int tx = threadIdx.x & 31, ty = threadIdx.x >> 5;
#pragma unroll
    for (int i = 0; i < 32; i += 8)
        tile[ty + i][tx] = w[(size_t)(k0 + ty + i) * N + n0 + tx];
    __syncthreads();
#pragma unroll
    for (int i = 0; i < 32; i += 8) {
        float v = tile[tx][ty + i];
        __nv_bfloat16 h = __float2bfloat16(v);
        __nv_bfloat16 l = __float2bfloat16(v - __bfloat162float(h));
        size_t o = (size_t)(n0 + ty + i) * K + k0 + tx;
        th[o] = h;
        tl[o] = l;
    }
}

// g_v [s][kvh][d] fp32 -> g_vth/g_vtl [kvh][d][s] bf16
__global__ void __launch_bounds__(256) vt_split() {
    __shared__ float tile[32][33];
    int s0 = blockIdx.x * 32, d0 = blockIdx.y * 32, kvh = blockIdx.z;
    int tx = threadIdx.x & 31, ty = threadIdx.x >> 5;
#pragma unroll
    for (int i = 0; i < 32; i += 8)
        tile[ty + i][tx] = g_v[((size_t)(s0 + ty + i) * NKV + kvh) * HD + d0 + tx];
    __syncthreads();
#pragma unroll
    for (int i = 0; i < 32; i += 8) {
        float v = tile[tx][ty + i];   // = v[s0+tx][d0+ty+i]
        __nv_bfloat16 h = __float2bfloat16(v);
        __nv_bfloat16 l = __float2bfloat16(v - __bfloat162float(h));
        size_t o = ((size_t)kvh * HD + d0 + ty + i) * SEQ + s0 + tx;
        g_vth[o] = h;
        g_vtl[o] = l;
    }
}

// ---------------------------------------------------------------------------
// Tensor-core bf16x3 GEMM via mma.sync, cp.async double-buffered.
//   C[M,N] fp32 = A[M,K] @ Bt[N,K]^T, D += Ah*Bh + Ah*Bl + Al*Bh
// CTA 128x128, BK=32, 8 warps (2x4), warp tile 64x32.
// ---------------------------------------------------------------------------
#define ASTR   40                       // bf16 per smem row (32 + 8 pad)
#define TILE_B (128 * ASTR * 2)         // bytes per [128][32] bf16 tile (10240)
#define STAGE_B (4 * TILE_B)            // 4 tiles per stage
#define GSM    (2 * STAGE_B)            // 81920 B dynamic smem

__device__ __forceinline__ void gemm_prefetch(
    uint32_t sbase, const __nv_bfloat16* Ah, const __nv_bfloat16* Al,
    const __nv_bfloat16* Bh, const __nv_bfloat16* Bl,
    int m0, int n0, int K, int k0, int tid)
{
#pragma unroll
    for (int i = 0; i < 2; i++) {
        int ch = tid + i * 256;              // 0..511
        int r = ch >> 2, c = (ch & 3) << 3;  // row, bf16-col
        uint32_t so = sbase + (uint32_t)(r * ASTR + c) * 2;
        size_t ga = (size_t)(m0 + r) * K + k0 + c;
        size_t gb = (size_t)(n0 + r) * K + k0 + c;
        cp16(so,              Ah + ga);
        cp16(so + TILE_B,     Al + ga);
        cp16(so + 2 * TILE_B, Bh + gb);
        cp16(so + 3 * TILE_B, Bl + gb);
    }
    CP_COMMIT();
}

__global__ void __launch_bounds__(256) gemm_mma(
    const __nv_bfloat16* __restrict__ Ah, const __nv_bfloat16* __restrict__ Al,
    const __nv_bfloat16* __restrict__ Bh, const __nv_bfloat16* __restrict__ Bl,
    float* __restrict__ C, int M, int N, int K)
{
    extern __shared__ char gsm[];
    uint32_t sb = smem_u32(gsm);

    int tid = threadIdx.x;
    int wid = tid >> 5, lane = tid & 31;
    int gr = lane >> 2, q = lane & 3;
    int warp_m = (wid >> 2) * 64;
    int warp_n = (wid & 3) * 32;
    int m0 = blockIdx.y * 128, n0 = blockIdx.x * 128;

    float acc[4][4][4];
#pragma unroll
    for (int mt = 0; mt < 4; mt++)
#pragma unroll
        for (int nt = 0; nt < 4; nt++)
#pragma unroll
            for (int r = 0; r < 4; r++) acc[mt][nt][r] = 0.f;

    int nIter = K >> 5;
    gemm_prefetch(sb, Ah, Al, Bh, Bl, m0, n0, K, 0, tid);

    for (int it = 0; it < nIter; it++) {
        int buf = it & 1;
        if (it + 1 < nIter) {
            gemm_prefetch(sb + (buf ^ 1) * STAGE_B, Ah, Al, Bh, Bl,
                          m0, n0, K, (it + 1) << 5, tid);
            CP_WAIT(1);
        } else {
            CP_WAIT(0);
        }
        __syncthreads();   // stage `buf` fully visible to all threads

        const __nv_bfloat16* sAh = (const __nv_bfloat16*)(gsm + buf * STAGE_B);
        const __nv_bfloat16* sAl = (const __nv_bfloat16*)(gsm + buf * STAGE_B + TILE_B);
        const __nv_bfloat16* sBh = (const __nv_bfloat16*)(gsm + buf * STAGE_B + 2 * TILE_B);
        const __nv_bfloat16* sBl = (const __nv_bfloat16*)(gsm + buf * STAGE_B + 3 * TILE_B);

#pragma unroll
        for (int ks = 0; ks < 2; ks++) {
            int kb = ks * 16 + 2 * q;
            uint32_t ah[4][4], al[4][4];
#pragma unroll
            for (int mt = 0; mt < 4; mt++) {
                int row = warp_m + mt * 16 + gr;
                const __nv_bfloat16* bh_ = sAh + row * ASTR + kb;
                const __nv_bfloat16* bl_ = sAl + row * ASTR + kb;
                ah[mt][0] = *(const uint32_t*)bh_;
                ah[mt][1] = *(const uint32_t*)(bh_ + 8 * ASTR);
                ah[mt][2] = *(const uint32_t*)(bh_ + 8);
                ah[mt][3] = *(const uint32_t*)(bh_ + 8 * ASTR + 8);
                al[mt][0] = *(const uint32_t*)bl_;
                al[mt][1] = *(const uint32_t*)(bl_ + 8 * ASTR);
                al[mt][2] = *(const uint32_t*)(bl_ + 8);
                al[mt][3] = *(const uint32_t*)(bl_ + 8 * ASTR + 8);
            }
#pragma unroll
            for (int nt = 0; nt < 4; nt++) {
                int col = warp_n + nt * 8 + gr;
                const __nv_bfloat16* pbh = sBh + col * ASTR + kb;
                const __nv_bfloat16* pbl = sBl + col * ASTR + kb;
                uint32_t bh0 = *(const uint32_t*)pbh;
                uint32_t bh1 = *(const uint32_t*)(pbh + 8);
                uint32_t bl0 = *(const uint32_t*)pbl;
                uint32_t bl1 = *(const uint32_t*)(pbl + 8);
#pragma unroll
                for (int mt = 0; mt < 4; mt++) {
                    mma16816(acc[mt][nt], ah[mt][0], ah[mt][1], ah[mt][2], ah[mt][3], bh0, bh1);
                    mma16816(acc[mt][nt], ah[mt][0], ah[mt][1], ah[mt][2], ah[mt][3], bl0, bl1);
                    mma16816(acc[mt][nt], al[mt][0], al[mt][1], al[mt][2], al[mt][3], bh0, bh1);
                }
            }
        }
        __syncthreads();   // compute on `buf` done before it is refilled
    }

#pragma unroll
    for (int mt = 0; mt < 4; mt++) {
#pragma unroll
        for (int nt = 0; nt < 4; nt++) {
            int row = m0 + warp_m + mt * 16 + gr;
            int col = n0 + warp_n + nt * 8 + 2 * q;
            *(float2*)(C + (size_t)row * N + col) = make_float2(acc[mt][nt][0], acc[mt][nt][1]);
            *(float2*)(C + (size_t)(row + 8) * N + col) = make_float2(acc[mt][nt][2], acc[mt][nt][3]);
        }
    }
}

// ---------------------------------------------------------------------------
// RoPE kernels (fp32, unchanged)
// ---------------------------------------------------------------------------
__global__ void rope_q_kernel(const float* __restrict__ cosb,
                              const float* __restrict__ sinb) {
    int idx = blockIdx.x * 256 + threadIdx.x;
    int i = idx & 31;
    int h = (idx >> 5) & (NH - 1);
    int s = idx >> 9;
    float c = cosb[s * RHALF + i];
    float sn = sinb[s * RHALF + i];
    float* p = g_q + ((size_t)s * NH + h) * HD;
    float x1 = p[i], x2 = p[i + RHALF];
    p[i] = x1 * c - x2 * sn;
    p[i + RHALF] = x1 * sn + x2 * c;
}

__global__ void rope_copy_k_v_kernel(const float* __restrict__ cosb,
                                     const float* __restrict__ sinb,
                                     float* __restrict__ out_k,
                                     float* __restrict__ out_v) {
    int idx = blockIdx.x * 256 + threadIdx.x;
    int t = idx & 127;
    int row = idx >> 7;
    int s = row >> 1;
    size_t base = (size_t)row * HD;
    float* kp = g_k + base;
    float* ok = out_k + base;

    if (t < 32) {
        float c = cosb[s * RHALF + t];
        float sn = sinb[s * RHALF + t];
        float x1 = kp[t], x2 = kp[t + RHALF];
        float r1 = x1 * c - x2 * sn;
        float r2 = x1 * sn + x2 * c;
        kp[t] = r1; kp[t + RHALF] = r2;
        ok[t] = r1; ok[t + RHALF] = r2;
    } else {
        int d = 64 + (t - 32) * 2;
        float2 x = *(const float2*)(kp + d);
        *(float2*)(ok + d) = x;
    }
    float2 v = *(const float2*)(g_v + base + t * 2);
    *(float2*)(out_v + base + t * 2) = v;
}

// ---------------------------------------------------------------------------
// Tensor-core flash attention (bf16x3), causal. BQ=64, BKEY=64.
// Grid (SEQ/64, NH), 256 threads. qb reversed for wave load balance.
// ---------------------------------------------------------------------------
#define QKS   264
#define VTS2  72
#define PSTR2 72
#define SSTR2 66

#define OFF_QH 0
#define OFF_QL 33792
#define OFF_KH 67584
#define OFF_KL 101376
#define OFF_VH 135168
#define OFF_VL 172032
#define OFF_PS 208896
#define OFF_ST 227328
#define ATT_SMEM 228096

__global__ void __launch_bounds__(256, 1) attn_mma(float scale) {
    extern __shared__ char smc[];
    __nv_bfloat16* sQh = (__nv_bfloat16*)(smc + OFF_QH);
    __nv_bfloat16* sQl = (__nv_bfloat16*)(smc + OFF_QL);
    __nv_bfloat16* sKh = (__nv_bfloat16*)(smc + OFF_KH);
    __nv_bfloat16* sKl = (__nv_bfloat16*)(smc + OFF_KL);
    __nv_bfloat16* sVh = (__nv_bfloat16*)(smc + OFF_VH);
    __nv_bfloat16* sVl = (__nv_bfloat16*)(smc + OFF_VL);
    float* sS = (float*)(smc + OFF_PS);              // unioned with Ph/Pl
    __nv_bfloat16* sPh = (__nv_bfloat16*)(smc + OFF_PS);
    __nv_bfloat16* sPl = sPh + 64 * PSTR2;
    float* mrow = (float*)(smc + OFF_ST);
    float* lrow = mrow + 64;
    float* arow = lrow + 64;

    int qb = gridDim.x - 1 - blockIdx.x;    // heavy causal tiles first
    int h = blockIdx.y, kvh = h / GQ;
    int tid = threadIdx.x, wid = tid >> 5, lane = tid & 31;
    int gr = lane >> 2, q = lane & 3;
    int mt = wid >> 1;
    int nh = wid & 1;
    int row0 = mt * 16 + gr;

    for (int t = tid; t < 2048; t += 256) {
        int r = t >> 5, c = (t & 31) << 3;
        size_t g = ((size_t)(qb * 64 + r) * NH + h) * HD + c;
        *(uint4*)(sQh + r * QKS + c) = *(const uint4*)(g_qh + g);
        *(uint4*)(sQl + r * QKS + c) = *(const uint4*)(g_ql + g);
    }
    if (tid < 64) { mrow[tid] = -1e30f; lrow[tid] = 0.f; }

    float o[16][4];
#pragma unroll
    for (int nt = 0; nt < 16; nt++)
#pragma unroll
        for (int r = 0; r < 4; r++) o[nt][r] = 0.f;

    int nkb = qb + 1;
    for (int kb = 0; kb < nkb; kb++) {
        __syncthreads();
        for (int t = tid; t < 2048; t += 256) {
            int r = t >> 5, c = (t & 31) << 3;
            size_t g = ((size_t)(kb * 64 + r) * NKV + kvh) * HD + c;
            *(uint4*)(sKh + r * QKS + c) = *(const uint4*)(g_kh + g);
            *(uint4*)(sKl + r * QKS + c) = *(const uint4*)(g_kl + g);
        }
        for (int t = tid; t < 2048; t += 256) {
            int r = t >> 3, c = (t & 7) << 3;
            size_t g = ((size_t)kvh * HD + r) * SEQ + kb * 64 + c;
            *(uint4*)(sVh + r * VTS2 + c) = *(const uint4*)(g_vth + g);
            *(uint4*)(sVl + r * VTS2 + c) = *(const uint4*)(g_vtl + g);
        }
        __syncthreads();

        // ---- S = Q K^T (m16 x n32 per warp), bf16x3 ----
        float sacc[4][4];
#pragma unroll
        for (int nt = 0; nt < 4; nt++)
#pragma unroll
            for (int r = 0; r < 4; r++) sacc[nt][r] = 0.f;

#pragma unroll 4
        for (int ks = 0; ks < 16; ks++) {
            int kk = ks * 16 + 2 * q;
            const __nv_bfloat16* qh_ = sQh + row0 * QKS + kk;
            const __nv_bfloat16* ql_ = sQl + row0 * QKS + kk;
            uint32_t ah0 = *(const uint32_t*)qh_;
            uint32_t ah1 = *(const uint32_t*)(qh_ + 8 * QKS);
            uint32_t ah2 = *(const uint32_t*)(qh_ + 8);
            uint32_t ah3 = *(const uint32_t*)(qh_ + 8 * QKS + 8);
            uint32_t al0 = *(const uint32_t*)ql_;
            uint32_t al1 = *(const uint32_t*)(ql_ + 8 * QKS);
            uint32_t al2 = *(const uint32_t*)(ql_ + 8);
            uint32_t al3 = *(const uint32_t*)(ql_ + 8 * QKS + 8);
#pragma unroll
            for (int nt = 0; nt < 4; nt++) {
                int col = nh * 32 + nt * 8 + gr;
                const __nv_bfloat16* kh_ = sKh + col * QKS + kk;
                const __nv_bfloat16* kl_ = sKl + col * QKS + kk;
                uint32_t bh0 = *(const uint32_t*)kh_;
                uint32_t bh1 = *(const uint32_t*)(kh_ + 8);
                uint32_t bl0 = *(const uint32_t*)kl_;
                uint32_t bl1 = *(const uint32_t*)(kl_ + 8);
                mma16816(sacc[nt], ah0, ah1, ah2, ah3, bh0, bh1);
                mma16816(sacc[nt], ah0, ah1, ah2, ah3, bl0, bl1);
                mma16816(sacc[nt], al0, al1, al2, al3, bh0, bh1);
            }
        }
        int rg0 = qb * 64 + row0, rg1 = rg0 + 8;
#pragma unroll
        for (int nt = 0; nt < 4; nt++) {
            int cl = nh * 32 + nt * 8 + 2 * q;
            int cg = kb * 64 + cl;
            sS[row0 * SSTR2 + cl]           = (cg     <= rg0) ? sacc[nt][0] * scale : -1e30f;
            sS[row0 * SSTR2 + cl + 1]       = (cg + 1 <= rg0) ? sacc[nt][1] * scale : -1e30f;
            sS[(row0 + 8) * SSTR2 + cl]     = (cg     <= rg1) ? sacc[nt][2] * scale : -1e30f;
            sS[(row0 + 8) * SSTR2 + cl + 1] = (cg + 1 <= rg1) ? sacc[nt][3] * scale : -1e30f;
        }
        __syncthreads();

        // ---- online softmax: 4 threads per row ----
        int srow = tid >> 2, sub = tid & 3;
        float sv[16];
        float mx = -1e30f;
#pragma unroll
        for (int j = 0; j < 16; j++) {
            sv[j] = sS[srow * SSTR2 + sub * 16 + j];
            mx = fmaxf(mx, sv[j]);
        }
        mx = fmaxf(mx, __shfl_xor_sync(0xffffffffu, mx, 1));
        mx = fmaxf(mx, __shfl_xor_sync(0xffffffffu, mx, 2));
        float m_old = mrow[srow];
        float mnew = fmaxf(m_old, mx);
        float al = __expf(m_old - mnew);
        float lsum = 0.f;
#pragma unroll
        for (int j = 0; j < 16; j++) {
            sv[j] = __expf(sv[j] - mnew);
            lsum += sv[j];
        }
        lsum += __shfl_xor_sync(0xffffffffu, lsum, 1);
        lsum += __shfl_xor_sync(0xffffffffu, lsum, 2);
        if (sub == 0) {
            mrow[srow] = mnew;
            arow[srow] = al;
            lrow[srow] = lrow[srow] * al + lsum;
        }
        __syncthreads();

#pragma unroll
        for (int j = 0; j < 16; j += 2) {
            float p0 = sv[j], p1 = sv[j + 1];
            __nv_bfloat16 h0 = __float2bfloat16(p0);
            __nv_bfloat16 h1 = __float2bfloat16(p1);
            *(uint32_t*)(sPh + srow * PSTR2 + sub * 16 + j) = pack2bf16(p0, p1);
            *(uint32_t*)(sPl + srow * PSTR2 + sub * 16 + j) =
                pack2bf16(p0 - __bfloat162float(h0), p1 - __bfloat162float(h1));
        }

        float a0 = arow[row0], a1 = arow[row0 + 8];
#pragma unroll
        for (int nt = 0; nt < 16; nt++) {
            o[nt][0] *= a0; o[nt][1] *= a0;
            o[nt][2] *= a1; o[nt][3] *= a1;
        }
        __syncthreads();

        // ---- O += P @ V (m16 x n128 per warp), bf16x3 ----
#pragma unroll
        for (int ks = 0; ks < 4; ks++) {
            int kk = ks * 16 + 2 * q;
            const __nv_bfloat16* ph_ = sPh + row0 * PSTR2 + kk;
            const __nv_bfloat16* pl_ = sPl + row0 * PSTR2 + kk;
            uint32_t ah0 = *(const uint32_t*)ph_;
            uint32_t ah1 = *(const uint32_t*)(ph_ + 8 * PSTR2);
            uint32_t ah2 = *(const uint32_t*)(ph_ + 8);
            uint32_t ah3 = *(const uint32_t*)(ph_ + 8 * PSTR2 + 8);
            uint32_t al0 = *(const uint32_t*)pl_;
            uint32_t al1 = *(const uint32_t*)(pl_ + 8 * PSTR2);
            uint32_t al2 = *(const uint32_t*)(pl_ + 8);
            uint32_t al3 = *(const uint32_t*)(pl_ + 8 * PSTR2 + 8);
#pragma unroll
            for (int nt = 0; nt < 16; nt++) {
                int drow = nh * 128 + nt * 8 + gr;
                const __nv_bfloat16* vh_ = sVh + drow * VTS2 + kk;
                const __nv_bfloat16* vl_ = sVl + drow * VTS2 + kk;
                uint32_t bh0 = *(const uint32_t*)vh_;
                uint32_t bh1 = *(const uint32_t*)(vh_ + 8);
                uint32_t bl0 = *(const uint32_t*)vl_;
                uint32_t bl1 = *(const uint32_t*)(vl_ + 8);
                mma16816(o[nt], ah0, ah1, ah2, ah3, bh0, bh1);
                mma16816(o[nt], ah0, ah1, ah2, ah3, bl0, bl1);
                mma16816(o[nt], al0, al1, al2, al3, bh0, bh1);
            }
        }
    }

    __syncthreads();
    float li0 = 1.f / lrow[row0], li1 = 1.f / lrow[row0 + 8];
#pragma unroll
    for (int nt = 0; nt < 16; nt++) {
        int col = nh * 128 + nt * 8 + 2 * q;
        size_t b0 = ((size_t)(qb * 64 + row0) * NH + h) * HD + col;
        size_t b1 = ((size_t)(qb * 64 + row0 + 8) * NH + h) * HD + col;
        float v0 = o[nt][0] * li0, v1 = o[nt][1] * li0;
        float v2 = o[nt][2] * li1, v3 = o[nt][3] * li1;
        __nv_bfloat16 h0 = __float2bfloat16(v0), h1 = __float2bfloat16(v1);
        __nv_bfloat16 h2 = __float2bfloat16(v2), h3 = __float2bfloat16(v3);
        *(uint32_t*)(g_ctxh + b0) = pack2bf16(v0, v1);
        *(uint32_t*)(g_ctxh + b1) = pack2bf16(v2, v3);
        *(uint32_t*)(g_ctxl + b0) = pack2bf16(v0 - __bfloat162float(h0), v1 - __bfloat162float(h1));
        *(uint32_t*)(g_ctxl + b1) = pack2bf16(v2 - __bfloat162float(h2), v3 - __bfloat162float(h3));
    }
}

// ---------------------------------------------------------------------------
// Launch
// ---------------------------------------------------------------------------
extern "C" void kernel_launch(void* const* d_in, const int* in_sizes, int n_in,
                              void* d_out, int out_size) {
    const float* hs   = (const float*)d_in[0];
    const float* cosb = (const float*)d_in[1];
    const float* sinb = (const float*)d_in[2];
    // d_in[3] = attention_mask (pure causal, applied analytically)
    const float* wq = (const float*)d_in[4];
    const float* wk = (const float*)d_in[5];
    const float* wv = (const float*)d_in[6];
    const float* wo = (const float*)d_in[7];

    float* out   = (float*)d_out;
    float* out_o = out;
    float* out_k = out + (size_t)SEQ * HIDDEN;
    float* out_v = out_k + (size_t)SEQ * NKV * HD;

    float *qp, *kp, *vp;
    cudaGetSymbolAddress((void**)&qp, g_q);
    cudaGetSymbolAddress((void**)&kp, g_k);
    cudaGetSymbolAddress((void**)&vp, g_v);
    __nv_bfloat16 *hsh, *hsl, *qh, *ql, *kh, *kl, *ctxh, *ctxl;
    __nv_bfloat16 *wqth, *wqtl, *wkth, *wktl, *wvth, *wvtl, *woth, *wotl;
    cudaGetSymbolAddress((void**)&hsh, g_hsh);   cudaGetSymbolAddress((void**)&hsl, g_hsl);
    cudaGetSymbolAddress((void**)&qh, g_qh);     cudaGetSymbolAddress((void**)&ql, g_ql);
    cudaGetSymbolAddress((void**)&kh, g_kh);     cudaGetSymbolAddress((void**)&kl, g_kl);
    cudaGetSymbolAddress((void**)&ctxh, g_ctxh); cudaGetSymbolAddress((void**)&ctxl, g_ctxl);
    cudaGetSymbolAddress((void**)&wqth, g_wqth); cudaGetSymbolAddress((void**)&wqtl, g_wqtl);
    cudaGetSymbolAddress((void**)&wkth, g_wkth); cudaGetSymbolAddress((void**)&wktl, g_wktl);
    cudaGetSymbolAddress((void**)&wvth, g_wvth); cudaGetSymbolAddress((void**)&wvtl, g_wvtl);
    cudaGetSymbolAddress((void**)&woth, g_woth); cudaGetSymbolAddress((void**)&wotl, g_wotl);

    cudaFuncSetAttribute(gemm_mma, cudaFuncAttributeMaxDynamicSharedMemorySize, GSM);

    // Prep: split activations, transpose+split weights
    split_hi_lo<<<(SEQ * HIDDEN / 4) / 256, 256>>>(hs, hsh, hsl);
    transpose_split<<<dim3((NH * HD) / 32, HIDDEN / 32), 256>>>(wq, wqth, wqtl, HIDDEN, NH * HD);
    transpose_split<<<dim3((NKV * HD) / 32, HIDDEN / 32), 256>>>(wk, wkth, wktl, HIDDEN, NKV * HD);
    transpose_split<<<dim3((NKV * HD) / 32, HIDDEN / 32), 256>>>(wv, wvth, wvtl, HIDDEN, NKV * HD);
    transpose_split<<<dim3(HIDDEN / 32, (NH * HD) / 32), 256>>>(wo, woth, wotl, NH * HD, HIDDEN);

    // Projections on tensor cores (bf16x3 via mma.sync, cp.async pipelined)
    gemm_mma<<<dim3((NH * HD) / 128, SEQ / 128), 256, GSM>>>(hsh, hsl, wqth, wqtl, qp, SEQ, NH * HD, HIDDEN);
    gemm_mma<<<dim3((NKV * HD) / 128, SEQ / 128), 256, GSM>>>(hsh, hsl, wkth, wktl, kp, SEQ, NKV * HD, HIDDEN);
    gemm_mma<<<dim3((NKV * HD) / 128, SEQ / 128), 256, GSM>>>(hsh, hsl, wvth, wvtl, vp, SEQ, NKV * HD, HIDDEN);

    // RoPE on Q; fused RoPE+copy for K, copy for V
    rope_q_kernel<<<(SEQ * NH * RHALF) / 256, 256>>>(cosb, sinb);
    rope_copy_k_v_kernel<<<(SEQ * NKV * 128) / 256, 256>>>(cosb, sinb, out_k, out_v);

    // hi/lo splits for attention operands
    split_hi_lo<<<((size_t)SEQ * NH * HD / 4) / 256, 256>>>(qp, qh, ql);
    split_hi_lo<<<((size_t)SEQ * NKV * HD / 4) / 256, 256>>>(kp, kh, kl);
    vt_split<<<dim3(SEQ / 32, HD / 32, NKV), 256>>>();

    // Tensor-core flash attention (writes ctx hi/lo directly)
    cudaFuncSetAttribute(attn_mma, cudaFuncAttributeMaxDynamicSharedMemorySize, ATT_SMEM);
    attn_mma<<<dim3(SEQ / 64, NH), 256, ATT_SMEM>>>(0.0625f);  // 256^-0.5

    // Output projection on tensor cores
    gemm_mma<<<dim3(HIDDEN / 128, SEQ / 128), 256, GSM>>>(ctxh, ctxl, woth, wotl, out_o, SEQ, HIDDEN, NH * HD);
}

// round 12
// speedup vs baseline: 1.3494x; 1.3494x over previous
#include <cuda_runtime.h>
#include <cuda_bf16.h>
#include <cstdint>

#define SEQ    4096
#define HIDDEN 2048
#define NH     16
#define NKV    2
#define HD     256
#define RHALF  32
#define GQ     (NH / NKV)

// ---------------------------------------------------------------------------
// Scratch (device globals — no allocations allowed)
// ---------------------------------------------------------------------------
__device__ float g_q[(size_t)SEQ * NH * HD];       // 64 MB
__device__ float g_k[(size_t)SEQ * NKV * HD];      // 8 MB
__device__ float g_v[(size_t)SEQ * NKV * HD];      // 8 MB

// bf16 hi/lo split operands
__device__ __nv_bfloat16 g_hsh[(size_t)SEQ * HIDDEN];
__device__ __nv_bfloat16 g_hsl[(size_t)SEQ * HIDDEN];
__device__ __nv_bfloat16 g_qh[(size_t)SEQ * NH * HD];
__device__ __nv_bfloat16 g_ql[(size_t)SEQ * NH * HD];
__device__ __nv_bfloat16 g_kh[(size_t)SEQ * NKV * HD];
__device__ __nv_bfloat16 g_kl[(size_t)SEQ * NKV * HD];
__device__ __nv_bfloat16 g_vth[(size_t)NKV * HD * SEQ];   // [kvh][d][s]
__device__ __nv_bfloat16 g_vtl[(size_t)NKV * HD * SEQ];
__device__ __nv_bfloat16 g_ctxh[(size_t)SEQ * NH * HD];   // attention out (hi/lo)
__device__ __nv_bfloat16 g_ctxl[(size_t)SEQ * NH * HD];
__device__ __nv_bfloat16 g_wqth[(size_t)(NH * HD) * HIDDEN];
__device__ __nv_bfloat16 g_wqtl[(size_t)(NH * HD) * HIDDEN];
__device__ __nv_bfloat16 g_wkth[(size_t)(NKV * HD) * HIDDEN];
__device__ __nv_bfloat16 g_wktl[(size_t)(NKV * HD) * HIDDEN];
__device__ __nv_bfloat16 g_wvth[(size_t)(NKV * HD) * HIDDEN];
__device__ __nv_bfloat16 g_wvtl[(size_t)(NKV * HD) * HIDDEN];
__device__ __nv_bfloat16 g_woth[(size_t)HIDDEN * (NH * HD)];
__device__ __nv_bfloat16 g_wotl[(size_t)HIDDEN * (NH * HD)];

// ---------------------------------------------------------------------------
// mma.sync m16n8k16 bf16 -> fp32 (baseline-PTX tensor path; verified R9/R10)
// ---------------------------------------------------------------------------
__device__ __forceinline__ void mma16816(float c[4],
                                         uint32_t a0, uint32_t a1, uint32_t a2, uint32_t a3,
                                         uint32_t b0, uint32_t b1) {
    asm volatile(
        "mma.sync.aligned.m16n8k16.row.col.f32.bf16.bf16.f32 "
        "{%0,%1,%2,%3}, {%4,%5,%6,%7}, {%8,%9}, {%0,%1,%2,%3};"
        : "+f"(c[0]), "+f"(c[1]), "+f"(c[2]), "+f"(c[3])
        : "r"(a0), "r"(a1), "r"(a2), "r"(a3), "r"(b0), "r"(b1));
}

__device__ __forceinline__ uint32_t pack2bf16(float a, float b) {
    __nv_bfloat162 t = __floats2bfloat162_rn(a, b);
    return *(uint32_t*)&t;
}

// ---------------------------------------------------------------------------
// Prep kernels
// ---------------------------------------------------------------------------
__global__ void __launch_bounds__(256) split_hi_lo(const float* __restrict__ x,
                                                   __nv_bfloat16* __restrict__ hi,
                                                   __nv_bfloat16* __restrict__ lo) {
    int i = blockIdx.x * 256 + threadIdx.x;
    float4 v = ((const float4*)x)[i];
    __nv_bfloat16 h0 = __float2bfloat16(v.x), h1 = __float2bfloat16(v.y);
    __nv_bfloat16 h2 = __float2bfloat16(v.z), h3 = __float2bfloat16(v.w);
    uint2 hp, lp;
    hp.x = pack2bf16(v.x, v.y); hp.y = pack2bf16(v.z, v.w);
    lp.x = pack2bf16(v.x - __bfloat162float(h0), v.y - __bfloat162float(h1));
    lp.y = pack2bf16(v.z - __bfloat162float(h2), v.w - __bfloat162float(h3));
    ((uint2*)hi)[i] = hp;
    ((uint2*)lo)[i] = lp;
}

// W [K][N] fp32 -> WT_hi/lo [N][K] bf16 (32x32 smem tile transpose)
__global__ void __launch_bounds__(256) transpose_split(const float* __restrict__ w,
                                                       __nv_bfloat16* __restrict__ th,
                                                       __nv_bfloat16* __restrict__ tl,
                                                       int K, int N) {
    __shared__ float tile[32][33];
    int n0 = blockIdx.x * 32, k0 = blockIdx.y * 32;
    int tx = threadIdx.x & 31, ty = threadIdx.x >> 5;
#pragma unroll
    for (int i = 0; i < 32; i += 8)
        tile[ty + i][tx] = w[(size_t)(k0 + ty + i) * N + n0 + tx];
    __syncthreads();
#pragma unroll
    for (int i = 0; i < 32; i += 8) {
        float v = tile[tx][ty + i];
        __nv_bfloat16 h = __float2bfloat16(v);
        __nv_bfloat16 l = __float2bfloat16(v - __bfloat162float(h));
        size_t o = (size_t)(n0 + ty + i) * K + k0 + tx;
        th[o] = h;
        tl[o] = l;
    }
}

// g_v [s][kvh][d] fp32 -> g_vth/g_vtl [kvh][d][s] bf16
__global__ void __launch_bounds__(256) vt_split() {
    __shared__ float tile[32][33];
    int s0 = blockIdx.x * 32, d0 = blockIdx.y * 32, kvh = blockIdx.z;
    int tx = threadIdx.x & 31, ty = threadIdx.x >> 5;
#pragma unroll
    for (int i = 0; i < 32; i += 8)
        tile[ty + i][tx] = g_v[((size_t)(s0 + ty + i) * NKV + kvh) * HD + d0 + tx];
    __syncthreads();
#pragma unroll
    for (int i = 0; i < 32; i += 8) {
        float v = tile[tx][ty + i];   // = v[s0+tx][d0+ty+i]
        __nv_bfloat16 h = __float2bfloat16(v);
        __nv_bfloat16 l = __float2bfloat16(v - __bfloat162float(h));
        size_t o = ((size_t)kvh * HD + d0 + ty + i) * SEQ + s0 + tx;
        g_vth[o] = h;
        g_vtl[o] = l;
    }
}

// ---------------------------------------------------------------------------
// Tensor-core bf16x3 GEMM via mma.sync (R10-verified single-buffer version:
// the cp.async double-buffer variant REGRESSED 3753->4999 us and was reverted)
//   C[M,N] fp32 = A[M,K] @ Bt[N,K]^T, D += Ah*Bh + Ah*Bl + Al*Bh
// CTA tile 128x128, BK=32. 8 warps (2x4), warp tile 64x32.
// ---------------------------------------------------------------------------
#define ASTR 40   // bf16 per smem row (32 + 8 pad) -> conflict-free pair loads

__global__ void __launch_bounds__(256) gemm_mma(
    const __nv_bfloat16* __restrict__ Ah, const __nv_bfloat16* __restrict__ Al,
    const __nv_bfloat16* __restrict__ Bh, const __nv_bfloat16* __restrict__ Bl,
    float* __restrict__ C, int M, int N, int K)
{
    __shared__ __nv_bfloat16 sAh[128 * ASTR];
    __shared__ __nv_bfloat16 sAl[128 * ASTR];
    __shared__ __nv_bfloat16 sBh[128 * ASTR];
    __shared__ __nv_bfloat16 sBl[128 * ASTR];

    int tid = threadIdx.x;
    int wid = tid >> 5, lane = tid & 31;
    int gr = lane >> 2, q = lane & 3;
    int warp_m = (wid >> 2) * 64;
    int warp_n = (wid & 3) * 32;
    int m0 = blockIdx.y * 128, n0 = blockIdx.x * 128;

    float acc[4][4][4];
#pragma unroll
    for (int mt = 0; mt < 4; mt++)
#pragma unroll
        for (int nt = 0; nt < 4; nt++)
#pragma unroll
            for (int r = 0; r < 4; r++) acc[mt][nt][r] = 0.f;

    for (int k0 = 0; k0 < K; k0 += 32) {
#pragma unroll
        for (int i = 0; i < 2; i++) {
            int ch = tid + i * 256;
            int r = ch >> 2, c = (ch & 3) << 3;
            int so = r * ASTR + c;
            *(uint4*)(sAh + so) = *(const uint4*)(Ah + (size_t)(m0 + r) * K + k0 + c);
            *(uint4*)(sAl + so) = *(const uint4*)(Al + (size_t)(m0 + r) * K + k0 + c);
            *(uint4*)(sBh + so) = *(const uint4*)(Bh + (size_t)(n0 + r) * K + k0 + c);
            *(uint4*)(sBl + so) = *(const uint4*)(Bl + (size_t)(n0 + r) * K + k0 + c);
        }
        __syncthreads();

#pragma unroll
        for (int ks = 0; ks < 2; ks++) {
            int kb = ks * 16 + 2 * q;
            uint32_t ah[4][4], al[4][4];
#pragma unroll
            for (int mt = 0; mt < 4; mt++) {
                int row = warp_m + mt * 16 + gr;
                const __nv_bfloat16* bh_ = sAh + row * ASTR + kb;
                const __nv_bfloat16* bl_ = sAl + row * ASTR + kb;
                ah[mt][0] = *(const uint32_t*)bh_;
                ah[mt][1] = *(const uint32_t*)(bh_ + 8 * ASTR);
                ah[mt][2] = *(const uint32_t*)(bh_ + 8);
                ah[mt][3] = *(const uint32_t*)(bh_ + 8 * ASTR + 8);
                al[mt][0] = *(const uint32_t*)bl_;
                al[mt][1] = *(const uint32_t*)(bl_ + 8 * ASTR);
                al[mt][2] = *(const uint32_t*)(bl_ + 8);
                al[mt][3] = *(const uint32_t*)(bl_ + 8 * ASTR + 8);
            }
#pragma unroll
            for (int nt = 0; nt < 4; nt++) {
                int col = warp_n + nt * 8 + gr;
                const __nv_bfloat16* pbh = sBh + col * ASTR + kb;
                const __nv_bfloat16* pbl = sBl + col * ASTR + kb;
                uint32_t bh0 = *(const uint32_t*)pbh;
                uint32_t bh1 = *(const uint32_t*)(pbh + 8);
                uint32_t bl0 = *(const uint32_t*)pbl;
                uint32_t bl1 = *(const uint32_t*)(pbl + 8);
#pragma unroll
                for (int mt = 0; mt < 4; mt++) {
                    mma16816(acc[mt][nt], ah[mt][0], ah[mt][1], ah[mt][2], ah[mt][3], bh0, bh1);
                    mma16816(acc[mt][nt], ah[mt][0], ah[mt][1], ah[mt][2], ah[mt][3], bl0, bl1);
                    mma16816(acc[mt][nt], al[mt][0], al[mt][1], al[mt][2], al[mt][3], bh0, bh1);
                }
            }
        }
        __syncthreads();
    }

#pragma unroll
    for (int mt = 0; mt < 4; mt++) {
#pragma unroll
        for (int nt = 0; nt < 4; nt++) {
            int row = m0 + warp_m + mt * 16 + gr;
            int col = n0 + warp_n + nt * 8 + 2 * q;
            *(float2*)(C + (size_t)row * N + col) = make_float2(acc[mt][nt][0], acc[mt][nt][1]);
            *(float2*)(C + (size_t)(row + 8) * N + col) = make_float2(acc[mt][nt][2], acc[mt][nt][3]);
        }
    }
}

// ---------------------------------------------------------------------------
// RoPE kernels (fp32, unchanged)
// ---------------------------------------------------------------------------
__global__ void rope_q_kernel(const float* __restrict__ cosb,
                              const float* __restrict__ sinb) {
    int idx = blockIdx.x * 256 + threadIdx.x;
    int i = idx & 31;
    int h = (idx >> 5) & (NH - 1);
    int s = idx >> 9;
    float c = cosb[s * RHALF + i];
    float sn = sinb[s * RHALF + i];
    float* p = g_q + ((size_t)s * NH + h) * HD;
    float x1 = p[i], x2 = p[i + RHALF];
    p[i] = x1 * c - x2 * sn;
    p[i + RHALF] = x1 * sn + x2 * c;
}

__global__ void rope_copy_k_v_kernel(const float* __restrict__ cosb,
                                     const float* __restrict__ sinb,
                                     float* __restrict__ out_k,
                                     float* __restrict__ out_v) {
    int idx = blockIdx.x * 256 + threadIdx.x;
    int t = idx & 127;
    int row = idx >> 7;
    int s = row >> 1;
    size_t base = (size_t)row * HD;
    float* kp = g_k + base;
    float* ok = out_k + base;

    if (t < 32) {
        float c = cosb[s * RHALF + t];
        float sn = sinb[s * RHALF + t];
        float x1 = kp[t], x2 = kp[t + RHALF];
        float r1 = x1 * c - x2 * sn;
        float r2 = x1 * sn + x2 * c;
        kp[t] = r1; kp[t + RHALF] = r2;
        ok[t] = r1; ok[t + RHALF] = r2;
    } else {
        int d = 64 + (t - 32) * 2;
        float2 x = *(const float2*)(kp + d);
        *(float2*)(ok + d) = x;
    }
    float2 v = *(const float2*)(g_v + base + t * 2);
    *(float2*)(out_v + base + t * 2) = v;
}

// ---------------------------------------------------------------------------
// Tensor-core flash attention (bf16x3), causal. BQ=64, BKEY=64.
// Grid (SEQ/64, NH), 256 threads. qb reversed for wave load balance.
// ---------------------------------------------------------------------------
#define QKS   264
#define VTS2  72
#define PSTR2 72
#define SSTR2 66

#define OFF_QH 0
#define OFF_QL 33792
#define OFF_KH 67584
#define OFF_KL 101376
#define OFF_VH 135168
#define OFF_VL 172032
#define OFF_PS 208896
#define OFF_ST 227328
#define ATT_SMEM 228096

__global__ void __launch_bounds__(256, 1) attn_mma(float scale) {
    extern __shared__ char smc[];
    __nv_bfloat16* sQh = (__nv_bfloat16*)(smc + OFF_QH);
    __nv_bfloat16* sQl = (__nv_bfloat16*)(smc + OFF_QL);
    __nv_bfloat16* sKh = (__nv_bfloat16*)(smc + OFF_KH);
    __nv_bfloat16* sKl = (__nv_bfloat16*)(smc + OFF_KL);
    __nv_bfloat16* sVh = (__nv_bfloat16*)(smc + OFF_VH);
    __nv_bfloat16* sVl = (__nv_bfloat16*)(smc + OFF_VL);
    float* sS = (float*)(smc + OFF_PS);              // unioned with Ph/Pl
    __nv_bfloat16* sPh = (__nv_bfloat16*)(smc + OFF_PS);
    __nv_bfloat16* sPl = sPh + 64 * PSTR2;
    float* mrow = (float*)(smc + OFF_ST);
    float* lrow = mrow + 64;
    float* arow = lrow + 64;

    int qb = gridDim.x - 1 - blockIdx.x;    // heavy causal tiles first
    int h = blockIdx.y, kvh = h / GQ;
    int tid = threadIdx.x, wid = tid >> 5, lane = tid & 31;
    int gr = lane >> 2, q = lane & 3;
    int mt = wid >> 1;
    int nh = wid & 1;
    int row0 = mt * 16 + gr;

    for (int t = tid; t < 2048; t += 256) {
        int r = t >> 5, c = (t & 31) << 3;
        size_t g = ((size_t)(qb * 64 + r) * NH + h) * HD + c;
        *(uint4*)(sQh + r * QKS + c) = *(const uint4*)(g_qh + g);
        *(uint4*)(sQl + r * QKS + c) = *(const uint4*)(g_ql + g);
    }
    if (tid < 64) { mrow[tid] = -1e30f; lrow[tid] = 0.f; }

    float o[16][4];
#pragma unroll
    for (int nt = 0; nt < 16; nt++)
#pragma unroll
        for (int r = 0; r < 4; r++) o[nt][r] = 0.f;

    int nkb = qb + 1;
    for (int kb = 0; kb < nkb; kb++) {
        __syncthreads();
        for (int t = tid; t < 2048; t += 256) {
            int r = t >> 5, c = (t & 31) << 3;
            size_t g = ((size_t)(kb * 64 + r) * NKV + kvh) * HD + c;
            *(uint4*)(sKh + r * QKS + c) = *(const uint4*)(g_kh + g);
            *(uint4*)(sKl + r * QKS + c) = *(const uint4*)(g_kl + g);
        }
        for (int t = tid; t < 2048; t += 256) {
            int r = t >> 3, c = (t & 7) << 3;
            size_t g = ((size_t)kvh * HD + r) * SEQ + kb * 64 + c;
            *(uint4*)(sVh + r * VTS2 + c) = *(const uint4*)(g_vth + g);
            *(uint4*)(sVl + r * VTS2 + c) = *(const uint4*)(g_vtl + g);
        }
        __syncthreads();

        // ---- S = Q K^T (m16 x n32 per warp), bf16x3 ----
        float sacc[4][4];
#pragma unroll
        for (int nt = 0; nt < 4; nt++)
#pragma unroll
            for (int r = 0; r < 4; r++) sacc[nt][r] = 0.f;

#pragma unroll 4
        for (int ks = 0; ks < 16; ks++) {
            int kk = ks * 16 + 2 * q;
            const __nv_bfloat16* qh_ = sQh + row0 * QKS + kk;
            const __nv_bfloat16* ql_ = sQl + row0 * QKS + kk;
            uint32_t ah0 = *(const uint32_t*)qh_;
            uint32_t ah1 = *(const uint32_t*)(qh_ + 8 * QKS);
            uint32_t ah2 = *(const uint32_t*)(qh_ + 8);
            uint32_t ah3 = *(const uint32_t*)(qh_ + 8 * QKS + 8);
            uint32_t al0 = *(const uint32_t*)ql_;
            uint32_t al1 = *(const uint32_t*)(ql_ + 8 * QKS);
            uint32_t al2 = *(const uint32_t*)(ql_ + 8);
            uint32_t al3 = *(const uint32_t*)(ql_ + 8 * QKS + 8);
#pragma unroll
            for (int nt = 0; nt < 4; nt++) {
                int col = nh * 32 + nt * 8 + gr;
                const __nv_bfloat16* kh_ = sKh + col * QKS + kk;
                const __nv_bfloat16* kl_ = sKl + col * QKS + kk;
                uint32_t bh0 = *(const uint32_t*)kh_;
                uint32_t bh1 = *(const uint32_t*)(kh_ + 8);
                uint32_t bl0 = *(const uint32_t*)kl_;
                uint32_t bl1 = *(const uint32_t*)(kl_ + 8);
                mma16816(sacc[nt], ah0, ah1, ah2, ah3, bh0, bh1);
                mma16816(sacc[nt], ah0, ah1, ah2, ah3, bl0, bl1);
                mma16816(sacc[nt], al0, al1, al2, al3, bh0, bh1);
            }
        }
        int rg0 = qb * 64 + row0, rg1 = rg0 + 8;
#pragma unroll
        for (int nt = 0; nt < 4; nt++) {
            int cl = nh * 32 + nt * 8 + 2 * q;
            int cg = kb * 64 + cl;
            sS[row0 * SSTR2 + cl]           = (cg     <= rg0) ? sacc[nt][0] * scale : -1e30f;
            sS[row0 * SSTR2 + cl + 1]       = (cg + 1 <= rg0) ? sacc[nt][1] * scale : -1e30f;
            sS[(row0 + 8) * SSTR2 + cl]     = (cg     <= rg1) ? sacc[nt][2] * scale : -1e30f;
            sS[(row0 + 8) * SSTR2 + cl + 1] = (cg + 1 <= rg1) ? sacc[nt][3] * scale : -1e30f;
        }
        __syncthreads();

        // ---- online softmax: 4 threads per row ----
        int srow = tid >> 2, sub = tid & 3;
        float sv[16];
        float mx = -1e30f;
#pragma unroll
        for (int j = 0; j < 16; j++) {
            sv[j] = sS[srow * SSTR2 + sub * 16 + j];
            mx = fmaxf(mx, sv[j]);
        }
        mx = fmaxf(mx, __shfl_xor_sync(0xffffffffu, mx, 1));
        mx = fmaxf(mx, __shfl_xor_sync(0xffffffffu, mx, 2));
        float m_old = mrow[srow];
        float mnew = fmaxf(m_old, mx);
        float al = __expf(m_old - mnew);
        float lsum = 0.f;
#pragma unroll
        for (int j = 0; j < 16; j++) {
            sv[j] = __expf(sv[j] - mnew);
            lsum += sv[j];
        }
        lsum += __shfl_xor_sync(0xffffffffu, lsum, 1);
        lsum += __shfl_xor_sync(0xffffffffu, lsum, 2);
        if (sub == 0) {
            mrow[srow] = mnew;
            arow[srow] = al;
            lrow[srow] = lrow[srow] * al + lsum;
        }
        __syncthreads();

#pragma unroll
        for (int j = 0; j < 16; j += 2) {
            float p0 = sv[j], p1 = sv[j + 1];
            __nv_bfloat16 h0 = __float2bfloat16(p0);
            __nv_bfloat16 h1 = __float2bfloat16(p1);
            *(uint32_t*)(sPh + srow * PSTR2 + sub * 16 + j) = pack2bf16(p0, p1);
            *(uint32_t*)(sPl + srow * PSTR2 + sub * 16 + j) =
                pack2bf16(p0 - __bfloat162float(h0), p1 - __bfloat162float(h1));
        }

        float a0 = arow[row0], a1 = arow[row0 + 8];
#pragma unroll
        for (int nt = 0; nt < 16; nt++) {
            o[nt][0] *= a0; o[nt][1] *= a0;
            o[nt][2] *= a1; o[nt][3] *= a1;
        }
        __syncthreads();

        // ---- O += P @ V (m16 x n128 per warp), bf16x3 ----
#pragma unroll
        for (int ks = 0; ks < 4; ks++) {
            int kk = ks * 16 + 2 * q;
            const __nv_bfloat16* ph_ = sPh + row0 * PSTR2 + kk;
            const __nv_bfloat16* pl_ = sPl + row0 * PSTR2 + kk;
            uint32_t ah0 = *(const uint32_t*)ph_;
            uint32_t ah1 = *(const uint32_t*)(ph_ + 8 * PSTR2);
            uint32_t ah2 = *(const uint32_t*)(ph_ + 8);
            uint32_t ah3 = *(const uint32_t*)(ph_ + 8 * PSTR2 + 8);
            uint32_t al0 = *(const uint32_t*)pl_;
            uint32_t al1 = *(const uint32_t*)(pl_ + 8 * PSTR2);
            uint32_t al2 = *(const uint32_t*)(pl_ + 8);
            uint32_t al3 = *(const uint32_t*)(pl_ + 8 * PSTR2 + 8);
#pragma unroll
            for (int nt = 0; nt < 16; nt++) {
                int drow = nh * 128 + nt * 8 + gr;
                const __nv_bfloat16* vh_ = sVh + drow * VTS2 + kk;
                const __nv_bfloat16* vl_ = sVl + drow * VTS2 + kk;
                uint32_t bh0 = *(const uint32_t*)vh_;
                uint32_t bh1 = *(const uint32_t*)(vh_ + 8);
                uint32_t bl0 = *(const uint32_t*)vl_;
                uint32_t bl1 = *(const uint32_t*)(vl_ + 8);
                mma16816(o[nt], ah0, ah1, ah2, ah3, bh0, bh1);
                mma16816(o[nt], ah0, ah1, ah2, ah3, bl0, bl1);
                mma16816(o[nt], al0, al1, al2, al3, bh0, bh1);
            }
        }
    }

    __syncthreads();
    float li0 = 1.f / lrow[row0], li1 = 1.f / lrow[row0 + 8];
#pragma unroll
    for (int nt = 0; nt < 16; nt++) {
        int col = nh * 128 + nt * 8 + 2 * q;
        size_t b0 = ((size_t)(qb * 64 + row0) * NH + h) * HD + col;
        size_t b1 = ((size_t)(qb * 64 + row0 + 8) * NH + h) * HD + col;
        float v0 = o[nt][0] * li0, v1 = o[nt][1] * li0;
        float v2 = o[nt][2] * li1, v3 = o[nt][3] * li1;
        __nv_bfloat16 h0 = __float2bfloat16(v0), h1 = __float2bfloat16(v1);
        __nv_bfloat16 h2 = __float2bfloat16(v2), h3 = __float2bfloat16(v3);
        *(uint32_t*)(g_ctxh + b0) = pack2bf16(v0, v1);
        *(uint32_t*)(g_ctxh + b1) = pack2bf16(v2, v3);
        *(uint32_t*)(g_ctxl + b0) = pack2bf16(v0 - __bfloat162float(h0), v1 - __bfloat162float(h1));
        *(uint32_t*)(g_ctxl + b1) = pack2bf16(v2 - __bfloat162float(h2), v3 - __bfloat162float(h3));
    }
}

// ---------------------------------------------------------------------------
// Launch. Order chosen so launch index 3 = gemm_mma(wq): the ncu capture
// window consistently profiles launch #3 (R6: rope_q; R9-R11: transpose),
// so this finally surfaces the dominant GEMM's roofline.
// ---------------------------------------------------------------------------
extern "C" void kernel_launch(void* const* d_in, const int* in_sizes, int n_in,
                              void* d_out, int out_size) {
    const float* hs   = (const float*)d_in[0];
    const float* cosb = (const float*)d_in[1];
    const float* sinb = (const float*)d_in[2];
    // d_in[3] = attention_mask (pure causal, applied analytically)
    const float* wq = (const float*)d_in[4];
    const float* wk = (const float*)d_in[5];
    const float* wv = (const float*)d_in[6];
    const float* wo = (const float*)d_in[7];

    float* out   = (float*)d_out;
    float* out_o = out;
    float* out_k = out + (size_t)SEQ * HIDDEN;
    float* out_v = out_k + (size_t)SEQ * NKV * HD;

    float *qp, *kp, *vp;
    cudaGetSymbolAddress((void**)&qp, g_q);
    cudaGetSymbolAddress((void**)&kp, g_k);
    cudaGetSymbolAddress((void**)&vp, g_v);
    __nv_bfloat16 *hsh, *hsl, *qh, *ql, *kh, *kl, *ctxh, *ctxl;
    __nv_bfloat16 *wqth, *wqtl, *wkth, *wktl, *wvth, *wvtl, *woth, *wotl;
    cudaGetSymbolAddress((void**)&hsh, g_hsh);   cudaGetSymbolAddress((void**)&hsl, g_hsl);
    cudaGetSymbolAddress((void**)&qh, g_qh);     cudaGetSymbolAddress((void**)&ql, g_ql);
    cudaGetSymbolAddress((void**)&kh, g_kh);     cudaGetSymbolAddress((void**)&kl, g_kl);
    cudaGetSymbolAddress((void**)&ctxh, g_ctxh); cudaGetSymbolAddress((void**)&ctxl, g_ctxl);
    cudaGetSymbolAddress((void**)&wqth, g_wqth); cudaGetSymbolAddress((void**)&wqtl, g_wqtl);
    cudaGetSymbolAddress((void**)&wkth, g_wkth); cudaGetSymbolAddress((void**)&wktl, g_wktl);
    cudaGetSymbolAddress((void**)&wvth, g_wvth); cudaGetSymbolAddress((void**)&wvtl, g_wvtl);
    cudaGetSymbolAddress((void**)&woth, g_woth); cudaGetSymbolAddress((void**)&wotl, g_wotl);

    // 0: split activations
    split_hi_lo<<<(SEQ * HIDDEN / 4) / 256, 256>>>(hs, hsh, hsl);
    // 1-2: transposes needed before the profiled gemm
    transpose_split<<<dim3((NH * HD) / 32, HIDDEN / 32), 256>>>(wq, wqth, wqtl, HIDDEN, NH * HD);
    transpose_split<<<dim3((NKV * HD) / 32, HIDDEN / 32), 256>>>(wk, wkth, wktl, HIDDEN, NKV * HD);
    // 3: Q projection — the launch the ncu window captures
    gemm_mma<<<dim3((NH * HD) / 128, SEQ / 128), 256>>>(hsh, hsl, wqth, wqtl, qp, SEQ, NH * HD, HIDDEN);
    // remaining prep + projections
    transpose_split<<<dim3((NKV * HD) / 32, HIDDEN / 32), 256>>>(wv, wvth, wvtl, HIDDEN, NKV * HD);
    transpose_split<<<dim3(HIDDEN / 32, (NH * HD) / 32), 256>>>(wo, woth, wotl, NH * HD, HIDDEN);
    gemm_mma<<<dim3((NKV * HD) / 128, SEQ / 128), 256>>>(hsh, hsl, wkth, wktl, kp, SEQ, NKV * HD, HIDDEN);
    gemm_mma<<<dim3((NKV * HD) / 128, SEQ / 128), 256>>>(hsh, hsl, wvth, wvtl, vp, SEQ, NKV * HD, HIDDEN);

    // RoPE on Q; fused RoPE+copy for K, copy for V
    rope_q_kernel<<<(SEQ * NH * RHALF) / 256, 256>>>(cosb, sinb);
    rope_copy_k_v_kernel<<<(SEQ * NKV * 128) / 256, 256>>>(cosb, sinb, out_k, out_v);

    // hi/lo splits for attention operands
    split_hi_lo<<<((size_t)SEQ * NH * HD / 4) / 256, 256>>>(qp, qh, ql);
    split_hi_lo<<<((size_t)SEQ * NKV * HD / 4) / 256, 256>>>(kp, kh, kl);
    vt_split<<<dim3(SEQ / 32, HD / 32, NKV), 256>>>();

    // Tensor-core flash attention (writes ctx hi/lo directly)
    cudaFuncSetAttribute(attn_mma, cudaFuncAttributeMaxDynamicSharedMemorySize, ATT_SMEM);
    attn_mma<<<dim3(SEQ / 64, NH), 256, ATT_SMEM>>>(0.0625f);  // 256^-0.5

    // Output projection on tensor cores
    gemm_mma<<<dim3(HIDDEN / 128, SEQ / 128), 256>>>(ctxh, ctxl, woth, wotl, out_o, SEQ, HIDDEN, NH * HD);
}

// round 13
// speedup vs baseline: 1.4520x; 1.0760x over previous
#include <cuda_runtime.h>
#include <cuda_bf16.h>
#include <cstdint>

#define SEQ    4096
#define HIDDEN 2048
#define NH     16
#define NKV    2
#define HD     256
#define RHALF  32
#define GQ     (NH / NKV)

// ---------------------------------------------------------------------------
// Scratch (device globals — no allocations allowed)
// ---------------------------------------------------------------------------
__device__ float g_q[(size_t)SEQ * NH * HD];       // 64 MB
__device__ float g_k[(size_t)SEQ * NKV * HD];      // 8 MB
__device__ float g_v[(size_t)SEQ * NKV * HD];      // 8 MB

// bf16 hi/lo split operands
__device__ __nv_bfloat16 g_hsh[(size_t)SEQ * HIDDEN];
__device__ __nv_bfloat16 g_hsl[(size_t)SEQ * HIDDEN];
__device__ __nv_bfloat16 g_qh[(size_t)SEQ * NH * HD];
__device__ __nv_bfloat16 g_ql[(size_t)SEQ * NH * HD];
__device__ __nv_bfloat16 g_kh[(size_t)SEQ * NKV * HD];
__device__ __nv_bfloat16 g_kl[(size_t)SEQ * NKV * HD];
__device__ __nv_bfloat16 g_vth[(size_t)NKV * HD * SEQ];   // [kvh][d][s]
__device__ __nv_bfloat16 g_vtl[(size_t)NKV * HD * SEQ];
__device__ __nv_bfloat16 g_ctxh[(size_t)SEQ * NH * HD];   // attention out (hi/lo)
__device__ __nv_bfloat16 g_ctxl[(size_t)SEQ * NH * HD];
__device__ __nv_bfloat16 g_wqth[(size_t)(NH * HD) * HIDDEN];
__device__ __nv_bfloat16 g_wqtl[(size_t)(NH * HD) * HIDDEN];
__device__ __nv_bfloat16 g_wkth[(size_t)(NKV * HD) * HIDDEN];
__device__ __nv_bfloat16 g_wktl[(size_t)(NKV * HD) * HIDDEN];
__device__ __nv_bfloat16 g_wvth[(size_t)(NKV * HD) * HIDDEN];
__device__ __nv_bfloat16 g_wvtl[(size_t)(NKV * HD) * HIDDEN];
__device__ __nv_bfloat16 g_woth[(size_t)HIDDEN * (NH * HD)];
__device__ __nv_bfloat16 g_wotl[(size_t)HIDDEN * (NH * HD)];

// ---------------------------------------------------------------------------
// mma.sync m16n8k16 bf16 -> fp32 (baseline-PTX tensor path; verified R9/R10)
// ---------------------------------------------------------------------------
__device__ __forceinline__ void mma16816(float c[4],
                                         uint32_t a0, uint32_t a1, uint32_t a2, uint32_t a3,
                                         uint32_t b0, uint32_t b1) {
    asm volatile(
        "mma.sync.aligned.m16n8k16.row.col.f32.bf16.bf16.f32 "
        "{%0,%1,%2,%3}, {%4,%5,%6,%7}, {%8,%9}, {%0,%1,%2,%3};"
        : "+f"(c[0]), "+f"(c[1]), "+f"(c[2]), "+f"(c[3])
        : "r"(a0), "r"(a1), "r"(a2), "r"(a3), "r"(b0), "r"(b1));
}

// ldmatrix x4: loads 4 8x8 b16 matrices; lane groups 0-7/8-15/16-23/24-31
// provide the row addresses of matrices 0/1/2/3 respectively.
#define LDM4(rg, ad) \
    asm volatile("ldmatrix.sync.aligned.m8n8.x4.shared.b16 {%0,%1,%2,%3}, [%4];" \
                 : "=r"((rg)[0]), "=r"((rg)[1]), "=r"((rg)[2]), "=r"((rg)[3]) \
                 : "r"(ad))

__device__ __forceinline__ uint32_t pack2bf16(float a, float b) {
    __nv_bfloat162 t = __floats2bfloat162_rn(a, b);
    return *(uint32_t*)&t;
}

__device__ __forceinline__ uint32_t smem_u32(const void* p) {
    uint32_t a;
    asm("{ .reg .u64 t; cvta.to.shared.u64 t, %1; cvt.u32.u64 %0, t; }"
        : "=r"(a) : "l"(p));
    return a;
}

// ---------------------------------------------------------------------------
// Prep kernels
// ---------------------------------------------------------------------------
__global__ void __launch_bounds__(256) split_hi_lo(const float* __restrict__ x,
                                                   __nv_bfloat16* __restrict__ hi,
                                                   __nv_bfloat16* __restrict__ lo) {
    int i = blockIdx.x * 256 + threadIdx.x;
    float4 v = ((const float4*)x)[i];
    __nv_bfloat16 h0 = __float2bfloat16(v.x), h1 = __float2bfloat16(v.y);
    __nv_bfloat16 h2 = __float2bfloat16(v.z), h3 = __float2bfloat16(v.w);
    uint2 hp, lp;
    hp.x = pack2bf16(v.x, v.y); hp.y = pack2bf16(v.z, v.w);
    lp.x = pack2bf16(v.x - __bfloat162float(h0), v.y - __bfloat162float(h1));
    lp.y = pack2bf16(v.z - __bfloat162float(h2), v.w - __bfloat162float(h3));
    ((uint2*)hi)[i] = hp;
    ((uint2*)lo)[i] = lp;
}

// W [K][N] fp32 -> WT_hi/lo [N][K] bf16 (32x32 smem tile transpose)
__global__ void __launch_bounds__(256) transpose_split(const float* __restrict__ w,
                                                       __nv_bfloat16* __restrict__ th,
                                                       __nv_bfloat16* __restrict__ tl,
                                                       int K, int N) {
    __shared__ float tile[32][33];
    int n0 = blockIdx.x * 32, k0 = blockIdx.y * 32;
    int tx = threadIdx.x & 31, ty = threadIdx.x >> 5;
#pragma unroll
    for (int i = 0; i < 32; i += 8)
        tile[ty + i][tx] = w[(size_t)(k0 + ty + i) * N + n0 + tx];
    __syncthreads();
#pragma unroll
    for (int i = 0; i < 32; i += 8) {
        float v = tile[tx][ty + i];
        __nv_bfloat16 h = __float2bfloat16(v);
        __nv_bfloat16 l = __float2bfloat16(v - __bfloat162float(h));
        size_t o = (size_t)(n0 + ty + i) * K + k0 + tx;
        th[o] = h;
        tl[o] = l;
    }
}

// g_v [s][kvh][d] fp32 -> g_vth/g_vtl [kvh][d][s] bf16
__global__ void __launch_bounds__(256) vt_split() {
    __shared__ float tile[32][33];
    int s0 = blockIdx.x * 32, d0 = blockIdx.y * 32, kvh = blockIdx.z;
    int tx = threadIdx.x & 31, ty = threadIdx.x >> 5;
#pragma unroll
    for (int i = 0; i < 32; i += 8)
        tile[ty + i][tx] = g_v[((size_t)(s0 + ty + i) * NKV + kvh) * HD + d0 + tx];
    __syncthreads();
#pragma unroll
    for (int i = 0; i < 32; i += 8) {
        float v = tile[tx][ty + i];   // = v[s0+tx][d0+ty+i]
        __nv_bfloat16 h = __float2bfloat16(v);
        __nv_bfloat16 l = __float2bfloat16(v - __bfloat162float(h));
        size_t o = ((size_t)kvh * HD + d0 + ty + i) * SEQ + s0 + tx;
        g_vth[o] = h;
        g_vtl[o] = l;
    }
}

// ---------------------------------------------------------------------------
// Tensor-core bf16x3 GEMM via mma.sync + ldmatrix.
//   C[M,N] fp32 = A[M,K] @ Bt[N,K]^T, D += Ah*Bh + Ah*Bl + Al*Bh
// CTA tile 128x128, BK=32. 512 threads / 16 warps (4x4), warp tile 32x32.
// R12 ncu: 256-thr version was occupancy-bound (occ=12.5%, tensor=41%,
// DRAM=1.8%) — this doubles warps/SMSP and cuts fragment-load issues 4x.
// ---------------------------------------------------------------------------
#define ASTR 40   // bf16 per smem row (32 + 8 pad); 80B row stride ->
                  // 8-row ldmatrix fetches are bank-conflict-free

__global__ void __launch_bounds__(512) gemm_mma(
    const __nv_bfloat16* __restrict__ Ah, const __nv_bfloat16* __restrict__ Al,
    const __nv_bfloat16* __restrict__ Bh, const __nv_bfloat16* __restrict__ Bl,
    float* __restrict__ C, int M, int N, int K)
{
    __shared__ __nv_bfloat16 sAh[128 * ASTR];
    __shared__ __nv_bfloat16 sAl[128 * ASTR];
    __shared__ __nv_bfloat16 sBh[128 * ASTR];
    __shared__ __nv_bfloat16 sBl[128 * ASTR];

    int tid = threadIdx.x;
    int wid = tid >> 5, lane = tid & 31;
    int gr = lane >> 2, q = lane & 3;
    int warp_m = (wid >> 2) * 32;   // 0,32,64,96
    int warp_n = (wid & 3) * 32;    // 0,32,64,96
    int m0 = blockIdx.y * 128, n0 = blockIdx.x * 128;

    // ldmatrix lane-relative byte offsets.
    // A (m16k16, x4): matrices {r0-7,k0-7},{r8-15,k0-7},{r0-7,k8-15},{r8-15,k8-15}
    uint32_t aoff = (uint32_t)((warp_m + (lane & 15)) * ASTR + ((lane >> 4) << 3)) * 2;
    // B (nt-pair, x4): {nt.b0, nt.b1, nt+1.b0, nt+1.b1}
    uint32_t boff = (uint32_t)((warp_n + (lane & 7) + ((lane >> 4) << 3)) * ASTR
                               + (((lane >> 3) & 1) << 3)) * 2;

    uint32_t baseAh = smem_u32(sAh) + aoff;
    uint32_t baseAl = smem_u32(sAl) + aoff;
    uint32_t baseBh = smem_u32(sBh) + boff;
    uint32_t baseBl = smem_u32(sBl) + boff;

    float acc[2][4][4];
#pragma unroll
    for (int mt = 0; mt < 2; mt++)
#pragma unroll
        for (int nt = 0; nt < 4; nt++)
#pragma unroll
            for (int r = 0; r < 4; r++) acc[mt][nt][r] = 0.f;

    int lr = tid >> 2, lc = (tid & 3) << 3;   // 512 thr: 1 chunk per tile each
    int lso = lr * ASTR + lc;

    for (int k0 = 0; k0 < K; k0 += 32) {
        *(uint4*)(sAh + lso) = *(const uint4*)(Ah + (size_t)(m0 + lr) * K + k0 + lc);
        *(uint4*)(sAl + lso) = *(const uint4*)(Al + (size_t)(m0 + lr) * K + k0 + lc);
        *(uint4*)(sBh + lso) = *(const uint4*)(Bh + (size_t)(n0 + lr) * K + k0 + lc);
        *(uint4*)(sBl + lso) = *(const uint4*)(Bl + (size_t)(n0 + lr) * K + k0 + lc);
        __syncthreads();

#pragma unroll
        for (int ks = 0; ks < 2; ks++) {
            uint32_t kbyte = (uint32_t)(ks * 16) * 2;
            uint32_t ah[2][4], al[2][4], bh[2][4], bl[2][4];
#pragma unroll
            for (int mt = 0; mt < 2; mt++) {
                uint32_t mo = (uint32_t)(mt * 16 * ASTR) * 2 + kbyte;
                LDM4(ah[mt], baseAh + mo);
                LDM4(al[mt], baseAl + mo);
            }
#pragma unroll
            for (int np = 0; np < 2; np++) {
                uint32_t no = (uint32_t)(np * 16 * ASTR) * 2 + kbyte;
                LDM4(bh[np], baseBh + no);
                LDM4(bl[np], baseBl + no);
            }
#pragma unroll
            for (int mt = 0; mt < 2; mt++)
#pragma unroll
                for (int nt = 0; nt < 4; nt++) {
                    int np = nt >> 1, hs = (nt & 1) << 1;
                    uint32_t b0h = bh[np][hs], b1h = bh[np][hs + 1];
                    uint32_t b0l = bl[np][hs], b1l = bl[np][hs + 1];
                    mma16816(acc[mt][nt], ah[mt][0], ah[mt][1], ah[mt][2], ah[mt][3], b0h, b1h);
                    mma16816(acc[mt][nt], ah[mt][0], ah[mt][1], ah[mt][2], ah[mt][3], b0l, b1l);
                    mma16816(acc[mt][nt], al[mt][0], al[mt][1], al[mt][2], al[mt][3], b0h, b1h);
                }
        }
        __syncthreads();
    }

#pragma unroll
    for (int mt = 0; mt < 2; mt++) {
#pragma unroll
        for (int nt = 0; nt < 4; nt++) {
            int row = m0 + warp_m + mt * 16 + gr;
            int col = n0 + warp_n + nt * 8 + 2 * q;
            *(float2*)(C + (size_t)row * N + col) = make_float2(acc[mt][nt][0], acc[mt][nt][1]);
            *(float2*)(C + (size_t)(row + 8) * N + col) = make_float2(acc[mt][nt][2], acc[mt][nt][3]);
        }
    }
}

// ---------------------------------------------------------------------------
// RoPE kernels (fp32, unchanged)
// ---------------------------------------------------------------------------
__global__ void rope_q_kernel(const float* __restrict__ cosb,
                              const float* __restrict__ sinb) {
    int idx = blockIdx.x * 256 + threadIdx.x;
    int i = idx & 31;
    int h = (idx >> 5) & (NH - 1);
    int s = idx >> 9;
    float c = cosb[s * RHALF + i];
    float sn = sinb[s * RHALF + i];
    float* p = g_q + ((size_t)s * NH + h) * HD;
    float x1 = p[i], x2 = p[i + RHALF];
    p[i] = x1 * c - x2 * sn;
    p[i + RHALF] = x1 * sn + x2 * c;
}

__global__ void rope_copy_k_v_kernel(const float* __restrict__ cosb,
                                     const float* __restrict__ sinb,
                                     float* __restrict__ out_k,
                                     float* __restrict__ out_v) {
    int idx = blockIdx.x * 256 + threadIdx.x;
    int t = idx & 127;
    int row = idx >> 7;
    int s = row >> 1;
    size_t base = (size_t)row * HD;
    float* kp = g_k + base;
    float* ok = out_k + base;

    if (t < 32) {
        float c = cosb[s * RHALF + t];
        float sn = sinb[s * RHALF + t];
        float x1 = kp[t], x2 = kp[t + RHALF];
        float r1 = x1 * c - x2 * sn;
        float r2 = x1 * sn + x2 * c;
        kp[t] = r1; kp[t + RHALF] = r2;
        ok[t] = r1; ok[t + RHALF] = r2;
    } else {
        int d = 64 + (t - 32) * 2;
        float2 x = *(const float2*)(kp + d);
        *(float2*)(ok + d) = x;
    }
    float2 v = *(const float2*)(g_v + base + t * 2);
    *(float2*)(out_v + base + t * 2) = v;
}

// ---------------------------------------------------------------------------
// Tensor-core flash attention (bf16x3), causal. BQ=64, BKEY=64.
// Grid (SEQ/64, NH), 256 threads. qb reversed for wave load balance.
// ---------------------------------------------------------------------------
#define QKS   264
#define VTS2  72
#define PSTR2 72
#define SSTR2 66

#define OFF_QH 0
#define OFF_QL 33792
#define OFF_KH 67584
#define OFF_KL 101376
#define OFF_VH 135168
#define OFF_VL 172032
#define OFF_PS 208896
#define OFF_ST 227328
#define ATT_SMEM 228096

__global__ void __launch_bounds__(256, 1) attn_mma(float scale) {
    extern __shared__ char smc[];
    __nv_bfloat16* sQh = (__nv_bfloat16*)(smc + OFF_QH);
    __nv_bfloat16* sQl = (__nv_bfloat16*)(smc + OFF_QL);
    __nv_bfloat16* sKh = (__nv_bfloat16*)(smc + OFF_KH);
    __nv_bfloat16* sKl = (__nv_bfloat16*)(smc + OFF_KL);
    __nv_bfloat16* sVh = (__nv_bfloat16*)(smc + OFF_VH);
    __nv_bfloat16* sVl = (__nv_bfloat16*)(smc + OFF_VL);
    float* sS = (float*)(smc + OFF_PS);              // unioned with Ph/Pl
    __nv_bfloat16* sPh = (__nv_bfloat16*)(smc + OFF_PS);
    __nv_bfloat16* sPl = sPh + 64 * PSTR2;
    float* mrow = (float*)(smc + OFF_ST);
    float* lrow = mrow + 64;
    float* arow = lrow + 64;

    int qb = gridDim.x - 1 - blockIdx.x;    // heavy causal tiles first
    int h = blockIdx.y, kvh = h / GQ;
    int tid = threadIdx.x, wid = tid >> 5, lane = tid & 31;
    int gr = lane >> 2, q = lane & 3;
    int mt = wid >> 1;
    int nh = wid & 1;
    int row0 = mt * 16 + gr;

    for (int t = tid; t < 2048; t += 256) {
        int r = t >> 5, c = (t & 31) << 3;
        size_t g = ((size_t)(qb * 64 + r) * NH + h) * HD + c;
        *(uint4*)(sQh + r * QKS + c) = *(const uint4*)(g_qh + g);
        *(uint4*)(sQl + r * QKS + c) = *(const uint4*)(g_ql + g);
    }
    if (tid < 64) { mrow[tid] = -1e30f; lrow[tid] = 0.f; }

    float o[16][4];
#pragma unroll
    for (int nt = 0; nt < 16; nt++)
#pragma unroll
        for (int r = 0; r < 4; r++) o[nt][r] = 0.f;

    int nkb = qb + 1;
    for (int kb = 0; kb < nkb; kb++) {
        __syncthreads();
        for (int t = tid; t < 2048; t += 256) {
            int r = t >> 5, c = (t & 31) << 3;
            size_t g = ((size_t)(kb * 64 + r) * NKV + kvh) * HD + c;
            *(uint4*)(sKh + r * QKS + c) = *(const uint4*)(g_kh + g);
            *(uint4*)(sKl + r * QKS + c) = *(const uint4*)(g_kl + g);
        }
        for (int t = tid; t < 2048; t += 256) {
            int r = t >> 3, c = (t & 7) << 3;
            size_t g = ((size_t)kvh * HD + r) * SEQ + kb * 64 + c;
            *(uint4*)(sVh + r * VTS2 + c) = *(const uint4*)(g_vth + g);
            *(uint4*)(sVl + r * VTS2 + c) = *(const uint4*)(g_vtl + g);
        }
        __syncthreads();

        // ---- S = Q K^T (m16 x n32 per warp), bf16x3 ----
        float sacc[4][4];
#pragma unroll
        for (int nt = 0; nt < 4; nt++)
#pragma unroll
            for (int r = 0; r < 4; r++) sacc[nt][r] = 0.f;

#pragma unroll 4
        for (int ks = 0; ks < 16; ks++) {
            int kk = ks * 16 + 2 * q;
            const __nv_bfloat16* qh_ = sQh + row0 * QKS + kk;
            const __nv_bfloat16* ql_ = sQl + row0 * QKS + kk;
            uint32_t ah0 = *(const uint32_t*)qh_;
            uint32_t ah1 = *(const uint32_t*)(qh_ + 8 * QKS);
            uint32_t ah2 = *(const uint32_t*)(qh_ + 8);
            uint32_t ah3 = *(const uint32_t*)(qh_ + 8 * QKS + 8);
            uint32_t al0 = *(const uint32_t*)ql_;
            uint32_t al1 = *(const uint32_t*)(ql_ + 8 * QKS);
            uint32_t al2 = *(const uint32_t*)(ql_ + 8);
            uint32_t al3 = *(const uint32_t*)(ql_ + 8 * QKS + 8);
#pragma unroll
            for (int nt = 0; nt < 4; nt++) {
                int col = nh * 32 + nt * 8 + gr;
                const __nv_bfloat16* kh_ = sKh + col * QKS + kk;
                const __nv_bfloat16* kl_ = sKl + col * QKS + kk;
                uint32_t bh0 = *(const uint32_t*)kh_;
                uint32_t bh1 = *(const uint32_t*)(kh_ + 8);
                uint32_t bl0 = *(const uint32_t*)kl_;
                uint32_t bl1 = *(const uint32_t*)(kl_ + 8);
                mma16816(sacc[nt], ah0, ah1, ah2, ah3, bh0, bh1);
                mma16816(sacc[nt], ah0, ah1, ah2, ah3, bl0, bl1);
                mma16816(sacc[nt], al0, al1, al2, al3, bh0, bh1);
            }
        }
        int rg0 = qb * 64 + row0, rg1 = rg0 + 8;
#pragma unroll
        for (int nt = 0; nt < 4; nt++) {
            int cl = nh * 32 + nt * 8 + 2 * q;
            int cg = kb * 64 + cl;
            sS[row0 * SSTR2 + cl]           = (cg     <= rg0) ? sacc[nt][0] * scale : -1e30f;
            sS[row0 * SSTR2 + cl + 1]       = (cg + 1 <= rg0) ? sacc[nt][1] * scale : -1e30f;
            sS[(row0 + 8) * SSTR2 + cl]     = (cg     <= rg1) ? sacc[nt][2] * scale : -1e30f;
            sS[(row0 + 8) * SSTR2 + cl + 1] = (cg + 1 <= rg1) ? sacc[nt][3] * scale : -1e30f;
        }
        __syncthreads();

        // ---- online softmax: 4 threads per row ----
        int srow = tid >> 2, sub = tid & 3;
        float sv[16];
        float mx = -1e30f;
#pragma unroll
        for (int j = 0; j < 16; j++) {
            sv[j] = sS[srow * SSTR2 + sub * 16 + j];
            mx = fmaxf(mx, sv[j]);
        }
        mx = fmaxf(mx, __shfl_xor_sync(0xffffffffu, mx, 1));
        mx = fmaxf(mx, __shfl_xor_sync(0xffffffffu, mx, 2));
        float m_old = mrow[srow];
        float mnew = fmaxf(m_old, mx);
        float al = __expf(m_old - mnew);
        float lsum = 0.f;
#pragma unroll
        for (int j = 0; j < 16; j++) {
            sv[j] = __expf(sv[j] - mnew);
            lsum += sv[j];
        }
        lsum += __shfl_xor_sync(0xffffffffu, lsum, 1);
        lsum += __shfl_xor_sync(0xffffffffu, lsum, 2);
        if (sub == 0) {
            mrow[srow] = mnew;
            arow[srow] = al;
            lrow[srow] = lrow[srow] * al + lsum;
        }
        __syncthreads();

#pragma unroll
        for (int j = 0; j < 16; j += 2) {
            float p0 = sv[j], p1 = sv[j + 1];
            __nv_bfloat16 h0 = __float2bfloat16(p0);
            __nv_bfloat16 h1 = __float2bfloat16(p1);
            *(uint32_t*)(sPh + srow * PSTR2 + sub * 16 + j) = pack2bf16(p0, p1);
            *(uint32_t*)(sPl + srow * PSTR2 + sub * 16 + j) =
                pack2bf16(p0 - __bfloat162float(h0), p1 - __bfloat162float(h1));
        }

        float a0 = arow[row0], a1 = arow[row0 + 8];
#pragma unroll
        for (int nt = 0; nt < 16; nt++) {
            o[nt][0] *= a0; o[nt][1] *= a0;
            o[nt][2] *= a1; o[nt][3] *= a1;
        }
        __syncthreads();

        // ---- O += P @ V (m16 x n128 per warp), bf16x3 ----
#pragma unroll
        for (int ks = 0; ks < 4; ks++) {
            int kk = ks * 16 + 2 * q;
            const __nv_bfloat16* ph_ = sPh + row0 * PSTR2 + kk;
            const __nv_bfloat16* pl_ = sPl + row0 * PSTR2 + kk;
            uint32_t ah0 = *(const uint32_t*)ph_;
            uint32_t ah1 = *(const uint32_t*)(ph_ + 8 * PSTR2);
            uint32_t ah2 = *(const uint32_t*)(ph_ + 8);
            uint32_t ah3 = *(const uint32_t*)(ph_ + 8 * PSTR2 + 8);
            uint32_t al0 = *(const uint32_t*)pl_;
            uint32_t al1 = *(const uint32_t*)(pl_ + 8 * PSTR2);
            uint32_t al2 = *(const uint32_t*)(pl_ + 8);
            uint32_t al3 = *(const uint32_t*)(pl_ + 8 * PSTR2 + 8);
#pragma unroll
            for (int nt = 0; nt < 16; nt++) {
                int drow = nh * 128 + nt * 8 + gr;
                const __nv_bfloat16* vh_ = sVh + drow * VTS2 + kk;
                const __nv_bfloat16* vl_ = sVl + drow * VTS2 + kk;
                uint32_t bh0 = *(const uint32_t*)vh_;
                uint32_t bh1 = *(const uint32_t*)(vh_ + 8);
                uint32_t bl0 = *(const uint32_t*)vl_;
                uint32_t bl1 = *(const uint32_t*)(vl_ + 8);
                mma16816(o[nt], ah0, ah1, ah2, ah3, bh0, bh1);
                mma16816(o[nt], ah0, ah1, ah2, ah3, bl0, bl1);
                mma16816(o[nt], al0, al1, al2, al3, bh0, bh1);
            }
        }
    }

    __syncthreads();
    float li0 = 1.f / lrow[row0], li1 = 1.f / lrow[row0 + 8];
#pragma unroll
    for (int nt = 0; nt < 16; nt++) {
        int col = nh * 128 + nt * 8 + 2 * q;
        size_t b0 = ((size_t)(qb * 64 + row0) * NH + h) * HD + col;
        size_t b1 = ((size_t)(qb * 64 + row0 + 8) * NH + h) * HD + col;
        float v0 = o[nt][0] * li0, v1 = o[nt][1] * li0;
        float v2 = o[nt][2] * li1, v3 = o[nt][3] * li1;
        __nv_bfloat16 h0 = __float2bfloat16(v0), h1 = __float2bfloat16(v1);
        __nv_bfloat16 h2 = __float2bfloat16(v2), h3 = __float2bfloat16(v3);
        *(uint32_t*)(g_ctxh + b0) = pack2bf16(v0, v1);
        *(uint32_t*)(g_ctxh + b1) = pack2bf16(v2, v3);
        *(uint32_t*)(g_ctxl + b0) = pack2bf16(v0 - __bfloat162float(h0), v1 - __bfloat162float(h1));
        *(uint32_t*)(g_ctxl + b1) = pack2bf16(v2 - __bfloat162float(h2), v3 - __bfloat162float(h3));
    }
}

// ---------------------------------------------------------------------------
// Launch. Order keeps launch index 3 = gemm_mma(wq) so the fixed ncu window
// (4th launch) keeps profiling the dominant GEMM across rounds.
// ---------------------------------------------------------------------------
extern "C" void kernel_launch(void* const* d_in, const int* in_sizes, int n_in,
                              void* d_out, int out_size) {
    const float* hs   = (const float*)d_in[0];
    const float* cosb = (const float*)d_in[1];
    const float* sinb = (const float*)d_in[2];
    // d_in[3] = attention_mask (pure causal, applied analytically)
    const float* wq = (const float*)d_in[4];
    const float* wk = (const float*)d_in[5];
    const float* wv = (const float*)d_in[6];
    const float* wo = (const float*)d_in[7];

    float* out   = (float*)d_out;
    float* out_o = out;
    float* out_k = out + (size_t)SEQ * HIDDEN;
    float* out_v = out_k + (size_t)SEQ * NKV * HD;

    float *qp, *kp, *vp;
    cudaGetSymbolAddress((void**)&qp, g_q);
    cudaGetSymbolAddress((void**)&kp, g_k);
    cudaGetSymbolAddress((void**)&vp, g_v);
    __nv_bfloat16 *hsh, *hsl, *qh, *ql, *kh, *kl, *ctxh, *ctxl;
    __nv_bfloat16 *wqth, *wqtl, *wkth, *wktl, *wvth, *wvtl, *woth, *wotl;
    cudaGetSymbolAddress((void**)&hsh, g_hsh);   cudaGetSymbolAddress((void**)&hsl, g_hsl);
    cudaGetSymbolAddress((void**)&qh, g_qh);     cudaGetSymbolAddress((void**)&ql, g_ql);
    cudaGetSymbolAddress((void**)&kh, g_kh);     cudaGetSymbolAddress((void**)&kl, g_kl);
    cudaGetSymbolAddress((void**)&ctxh, g_ctxh); cudaGetSymbolAddress((void**)&ctxl, g_ctxl);
    cudaGetSymbolAddress((void**)&wqth, g_wqth); cudaGetSymbolAddress((void**)&wqtl, g_wqtl);
    cudaGetSymbolAddress((void**)&wkth, g_wkth); cudaGetSymbolAddress((void**)&wktl, g_wktl);
    cudaGetSymbolAddress((void**)&wvth, g_wvth); cudaGetSymbolAddress((void**)&wvtl, g_wvtl);
    cudaGetSymbolAddress((void**)&woth, g_woth); cudaGetSymbolAddress((void**)&wotl, g_wotl);

    // 0: split activations
    split_hi_lo<<<(SEQ * HIDDEN / 4) / 256, 256>>>(hs, hsh, hsl);
    // 1-2: transposes needed before the profiled gemm
    transpose_split<<<dim3((NH * HD) / 32, HIDDEN / 32), 256>>>(wq, wqth, wqtl, HIDDEN, NH * HD);
    transpose_split<<<dim3((NKV * HD) / 32, HIDDEN / 32), 256>>>(wk, wkth, wktl, HIDDEN, NKV * HD);
    // 3: Q projection — the launch the ncu window captures
    gemm_mma<<<dim3((NH * HD) / 128, SEQ / 128), 512>>>(hsh, hsl, wqth, wqtl, qp, SEQ, NH * HD, HIDDEN);
    // remaining prep + projections
    transpose_split<<<dim3((NKV * HD) / 32, HIDDEN / 32), 256>>>(wv, wvth, wvtl, HIDDEN, NKV * HD);
    transpose_split<<<dim3(HIDDEN / 32, (NH * HD) / 32), 256>>>(wo, woth, wotl, NH * HD, HIDDEN);
    gemm_mma<<<dim3((NKV * HD) / 128, SEQ / 128), 512>>>(hsh, hsl, wkth, wktl, kp, SEQ, NKV * HD, HIDDEN);
    gemm_mma<<<dim3((NKV * HD) / 128, SEQ / 128), 512>>>(hsh, hsl, wvth, wvtl, vp, SEQ, NKV * HD, HIDDEN);

    // RoPE on Q; fused RoPE+copy for K, copy for V
    rope_q_kernel<<<(SEQ * NH * RHALF) / 256, 256>>>(cosb, sinb);
    rope_copy_k_v_kernel<<<(SEQ * NKV * 128) / 256, 256>>>(cosb, sinb, out_k, out_v);

    // hi/lo splits for attention operands
    split_hi_lo<<<((size_t)SEQ * NH * HD / 4) / 256, 256>>>(qp, qh, ql);
    split_hi_lo<<<((size_t)SEQ * NKV * HD / 4) / 256, 256>>>(kp, kh, kl);
    vt_split<<<dim3(SEQ / 32, HD / 32, NKV), 256>>>();

    // Tensor-core flash attention (writes ctx hi/lo directly)
    cudaFuncSetAttribute(attn_mma, cudaFuncAttributeMaxDynamicSharedMemorySize, ATT_SMEM);
    attn_mma<<<dim3(SEQ / 64, NH), 256, ATT_SMEM>>>(0.0625f);  // 256^-0.5

    // Output projection on tensor cores
    gemm_mma<<<dim3(HIDDEN / 128, SEQ / 128), 512>>>(ctxh, ctxl, woth, wotl, out_o, SEQ, HIDDEN, NH * HD);
}

// round 15
// speedup vs baseline: 1.5025x; 1.0348x over previous
#include <cuda_runtime.h>
#include <cuda_bf16.h>
#include <cstdint>

#define SEQ    4096
#define HIDDEN 2048
#define NH     16
#define NKV    2
#define HD     256
#define RHALF  32
#define GQ     (NH / NKV)

// ---------------------------------------------------------------------------
// Scratch (device globals — no allocations allowed)
// ---------------------------------------------------------------------------
__device__ float g_q[(size_t)SEQ * NH * HD];
__device__ float g_k[(size_t)SEQ * NKV * HD];
__device__ float g_v[(size_t)SEQ * NKV * HD];

__device__ __nv_bfloat16 g_hsh[(size_t)SEQ * HIDDEN];
__device__ __nv_bfloat16 g_hsl[(size_t)SEQ * HIDDEN];
__device__ __nv_bfloat16 g_qh[(size_t)SEQ * NH * HD];
__device__ __nv_bfloat16 g_ql[(size_t)SEQ * NH * HD];
__device__ __nv_bfloat16 g_kh[(size_t)SEQ * NKV * HD];
__device__ __nv_bfloat16 g_kl[(size_t)SEQ * NKV * HD];
__device__ __nv_bfloat16 g_vth[(size_t)NKV * HD * SEQ];   // [kvh][d][s]
__device__ __nv_bfloat16 g_vtl[(size_t)NKV * HD * SEQ];
__device__ __nv_bfloat16 g_ctxh[(size_t)SEQ * NH * HD];
__device__ __nv_bfloat16 g_ctxl[(size_t)SEQ * NH * HD];
__device__ __nv_bfloat16 g_wqth[(size_t)(NH * HD) * HIDDEN];
__device__ __nv_bfloat16 g_wqtl[(size_t)(NH * HD) * HIDDEN];
__device__ __nv_bfloat16 g_wkth[(size_t)(NKV * HD) * HIDDEN];
__device__ __nv_bfloat16 g_wktl[(size_t)(NKV * HD) * HIDDEN];
__device__ __nv_bfloat16 g_wvth[(size_t)(NKV * HD) * HIDDEN];
__device__ __nv_bfloat16 g_wvtl[(size_t)(NKV * HD) * HIDDEN];
__device__ __nv_bfloat16 g_woth[(size_t)HIDDEN * (NH * HD)];
__device__ __nv_bfloat16 g_wotl[(size_t)HIDDEN * (NH * HD)];

// ---------------------------------------------------------------------------
// mma.sync m16n8k16 bf16 -> fp32 + ldmatrix (baseline-PTX tensor path)
// ---------------------------------------------------------------------------
__device__ __forceinline__ void mma16816(float c[4],
                                         uint32_t a0, uint32_t a1, uint32_t a2, uint32_t a3,
                                         uint32_t b0, uint32_t b1) {
    asm volatile(
        "mma.sync.aligned.m16n8k16.row.col.f32.bf16.bf16.f32 "
        "{%0,%1,%2,%3}, {%4,%5,%6,%7}, {%8,%9}, {%0,%1,%2,%3};"
        : "+f"(c[0]), "+f"(c[1]), "+f"(c[2]), "+f"(c[3])
        : "r"(a0), "r"(a1), "r"(a2), "r"(a3), "r"(b0), "r"(b1));
}

#define LDM4(rg, ad) \
    asm volatile("ldmatrix.sync.aligned.m8n8.x4.shared.b16 {%0,%1,%2,%3}, [%4];" \
                 : "=r"((rg)[0]), "=r"((rg)[1]), "=r"((rg)[2]), "=r"((rg)[3]) \
                 : "r"(ad))

__device__ __forceinline__ uint32_t pack2bf16(float a, float b) {
    __nv_bfloat162 t = __floats2bfloat162_rn(a, b);
    return *(uint32_t*)&t;
}

__device__ __forceinline__ uint32_t smem_u32(const void* p) {
    uint32_t a;
    asm("{ .reg .u64 t; cvta.to.shared.u64 t, %1; cvt.u32.u64 %0, t; }"
        : "=r"(a) : "l"(p));
    return a;
}

// ---------------------------------------------------------------------------
// Prep kernels
// ---------------------------------------------------------------------------
__global__ void __launch_bounds__(256) split_hi_lo(const float* __restrict__ x,
                                                   __nv_bfloat16* __restrict__ hi,
                                                   __nv_bfloat16* __restrict__ lo) {
    int i = blockIdx.x * 256 + threadIdx.x;
    float4 v = ((const float4*)x)[i];
    __nv_bfloat16 h0 = __float2bfloat16(v.x), h1 = __float2bfloat16(v.y);
    __nv_bfloat16 h2 = __float2bfloat16(v.z), h3 = __float2bfloat16(v.w);
    uint2 hp, lp;
    hp.x = pack2bf16(v.x, v.y); hp.y = pack2bf16(v.z, v.w);
    lp.x = pack2bf16(v.x - __bfloat162float(h0), v.y - __bfloat162float(h1));
    lp.y = pack2bf16(v.z - __bfloat162float(h2), v.w - __bfloat162float(h3));
    ((uint2*)hi)[i] = hp;
    ((uint2*)lo)[i] = lp;
}

__global__ void __launch_bounds__(256) transpose_split(const float* __restrict__ w,
                                                       __nv_bfloat16* __restrict__ th,
                                                       __nv_bfloat16* __restrict__ tl,
                                                       int K, int N) {
    __shared__ float tile[32][33];
    int n0 = blockIdx.x * 32, k0 = blockIdx.y * 32;
    int tx = threadIdx.x & 31, ty = threadIdx.x >> 5;
#pragma unroll
    for (int i = 0; i < 32; i += 8)
        tile[ty + i][tx] = w[(size_t)(k0 + ty + i) * N + n0 + tx];
    __syncthreads();
#pragma unroll
    for (int i = 0; i < 32; i += 8) {
        float v = tile[tx][ty + i];
        __nv_bfloat16 h = __float2bfloat16(v);
        __nv_bfloat16 l = __float2bfloat16(v - __bfloat162float(h));
        size_t o = (size_t)(n0 + ty + i) * K + k0 + tx;
        th[o] = h;
        tl[o] = l;
    }
}

__global__ void __launch_bounds__(256) vt_split() {
    __shared__ float tile[32][33];
    int s0 = blockIdx.x * 32, d0 = blockIdx.y * 32, kvh = blockIdx.z;
    int tx = threadIdx.x & 31, ty = threadIdx.x >> 5;
#pragma unroll
    for (int i = 0; i < 32; i += 8)
        tile[ty + i][tx] = g_v[((size_t)(s0 + ty + i) * NKV + kvh) * HD + d0 + tx];
    __syncthreads();
#pragma unroll
    for (int i = 0; i < 32; i += 8) {
        float v = tile[tx][ty + i];
        __nv_bfloat16 h = __float2bfloat16(v);
        __nv_bfloat16 l = __float2bfloat16(v - __bfloat162float(h));
        size_t o = ((size_t)kvh * HD + d0 + ty + i) * SEQ + s0 + tx;
        g_vth[o] = h;
        g_vtl[o] = l;
    }
}

#define ASTR 40   // bf16 per smem row (32 + 8 pad); 80B stride conflict-free

// ---------------------------------------------------------------------------
// gemm_mma: 128x128 CTA tile, 512 thr, warp 32x32 (R13-verified). For wk/wv.
// ---------------------------------------------------------------------------
__global__ void __launch_bounds__(512) gemm_mma(
    const __nv_bfloat16* __restrict__ Ah, const __nv_bfloat16* __restrict__ Al,
    const __nv_bfloat16* __restrict__ Bh, const __nv_bfloat16* __restrict__ Bl,
    float* __restrict__ C, int M, int N, int K)
{
    __shared__ __nv_bfloat16 sAh[128 * ASTR];
    __shared__ __nv_bfloat16 sAl[128 * ASTR];
    __shared__ __nv_bfloat16 sBh[128 * ASTR];
    __shared__ __nv_bfloat16 sBl[128 * ASTR];

    int tid = threadIdx.x;
    int wid = tid >> 5, lane = tid & 31;
    int gr = lane >> 2, q = lane & 3;
    int warp_m = (wid >> 2) * 32;
    int warp_n = (wid & 3) * 32;
    int m0 = blockIdx.y * 128, n0 = blockIdx.x * 128;

    uint32_t aoff = (uint32_t)((warp_m + (lane & 15)) * ASTR + ((lane >> 4) << 3)) * 2;
    uint32_t boff = (uint32_t)((warp_n + (lane & 7) + ((lane >> 4) << 3)) * ASTR
                               + (((lane >> 3) & 1) << 3)) * 2;

    uint32_t baseAh = smem_u32(sAh) + aoff;
    uint32_t baseAl = smem_u32(sAl) + aoff;
    uint32_t baseBh = smem_u32(sBh) + boff;
    uint32_t baseBl = smem_u32(sBl) + boff;

    float acc[2][4][4];
#pragma unroll
    for (int mt = 0; mt < 2; mt++)
#pragma unroll
        for (int nt = 0; nt < 4; nt++)
#pragma unroll
            for (int r = 0; r < 4; r++) acc[mt][nt][r] = 0.f;

    int lr = tid >> 2, lc = (tid & 3) << 3;
    int lso = lr * ASTR + lc;

    for (int k0 = 0; k0 < K; k0 += 32) {
        *(uint4*)(sAh + lso) = *(const uint4*)(Ah + (size_t)(m0 + lr) * K + k0 + lc);
        *(uint4*)(sAl + lso) = *(const uint4*)(Al + (size_t)(m0 + lr) * K + k0 + lc);
        *(uint4*)(sBh + lso) = *(const uint4*)(Bh + (size_t)(n0 + lr) * K + k0 + lc);
        *(uint4*)(sBl + lso) = *(const uint4*)(Bl + (size_t)(n0 + lr) * K + k0 + lc);
        __syncthreads();

#pragma unroll
        for (int ks = 0; ks < 2; ks++) {
            uint32_t kbyte = (uint32_t)(ks * 16) * 2;
            uint32_t ah[2][4], al[2][4], bh[2][4], bl[2][4];
#pragma unroll
            for (int mt = 0; mt < 2; mt++) {
                uint32_t mo = (uint32_t)(mt * 16 * ASTR) * 2 + kbyte;
                LDM4(ah[mt], baseAh + mo);
                LDM4(al[mt], baseAl + mo);
            }
#pragma unroll
            for (int np = 0; np < 2; np++) {
                uint32_t no = (uint32_t)(np * 16 * ASTR) * 2 + kbyte;
                LDM4(bh[np], baseBh + no);
                LDM4(bl[np], baseBl + no);
            }
#pragma unroll
            for (int mt = 0; mt < 2; mt++)
#pragma unroll
                for (int nt = 0; nt < 4; nt++) {
                    int np = nt >> 1, hs = (nt & 1) << 1;
                    uint32_t b0h = bh[np][hs], b1h = bh[np][hs + 1];
                    uint32_t b0l = bl[np][hs], b1l = bl[np][hs + 1];
                    mma16816(acc[mt][nt], ah[mt][0], ah[mt][1], ah[mt][2], ah[mt][3], b0h, b1h);
                    mma16816(acc[mt][nt], ah[mt][0], ah[mt][1], ah[mt][2], ah[mt][3], b0l, b1l);
                    mma16816(acc[mt][nt], al[mt][0], al[mt][1], al[mt][2], al[mt][3], b0h, b1h);
                }
        }
        __syncthreads();
    }

#pragma unroll
    for (int mt = 0; mt < 2; mt++) {
#pragma unroll
        for (int nt = 0; nt < 4; nt++) {
            int row = m0 + warp_m + mt * 16 + gr;
            int col = n0 + warp_n + nt * 8 + 2 * q;
            *(float2*)(C + (size_t)row * N + col) = make_float2(acc[mt][nt][0], acc[mt][nt][1]);
            *(float2*)(C + (size_t)(row + 8) * N + col) = make_float2(acc[mt][nt][2], acc[mt][nt][3]);
        }
    }
}

// ---------------------------------------------------------------------------
// gemm_mma_big: 256x128 CTA tile, 512 thr / 16 warps (4x4), warp 64x32.
// Better fragment reuse (LDM4/MMA 0.33 -> 0.25) to relieve the L1=65% limit
// seen in R13. Dynamic smem (60KB > 48KB static cap). For wq/wo.
// ---------------------------------------------------------------------------
#define BTILE_A (256 * ASTR * 2)   // 20480 B per A tile
#define BTILE_B (128 * ASTR * 2)   // 10240 B per B tile
#define GSMB (2 * BTILE_A + 2 * BTILE_B)   // 61440 B

__global__ void __launch_bounds__(512, 1) gemm_mma_big(
    const __nv_bfloat16* __restrict__ Ah, const __nv_bfloat16* __restrict__ Al,
    const __nv_bfloat16* __restrict__ Bh, const __nv_bfloat16* __restrict__ Bl,
    float* __restrict__ C, int M, int N, int K)
{
    extern __shared__ char gsm[];
    __nv_bfloat16* sAh = (__nv_bfloat16*)gsm;
    __nv_bfloat16* sAl = (__nv_bfloat16*)(gsm + BTILE_A);
    __nv_bfloat16* sBh = (__nv_bfloat16*)(gsm + 2 * BTILE_A);
    __nv_bfloat16* sBl = (__nv_bfloat16*)(gsm + 2 * BTILE_A + BTILE_B);

    int tid = threadIdx.x;
    int wid = tid >> 5, lane = tid & 31;
    int gr = lane >> 2, q = lane & 3;
    int warp_m = (wid >> 2) * 64;   // 0,64,128,192
    int warp_n = (wid & 3) * 32;    // 0,32,64,96
    int m0 = blockIdx.y * 256, n0 = blockIdx.x * 128;

    uint32_t aoff = (uint32_t)((warp_m + (lane & 15)) * ASTR + ((lane >> 4) << 3)) * 2;
    uint32_t boff = (uint32_t)((warp_n + (lane & 7) + ((lane >> 4) << 3)) * ASTR
                               + (((lane >> 3) & 1) << 3)) * 2;

    uint32_t baseAh = smem_u32(sAh) + aoff;
    uint32_t baseAl = smem_u32(sAl) + aoff;
    uint32_t baseBh = smem_u32(sBh) + boff;
    uint32_t baseBl = smem_u32(sBl) + boff;

    float acc[4][4][4];
#pragma unroll
    for (int mt = 0; mt < 4; mt++)
#pragma unroll
        for (int nt = 0; nt < 4; nt++)
#pragma unroll
            for (int r = 0; r < 4; r++) acc[mt][nt][r] = 0.f;

    int lrA = tid >> 2, lcA = (tid & 3) << 3;          // A: 2 chunks/thread
    int lrB = tid >> 2, lcB = (tid & 3) << 3;          // B: 1 chunk/thread

    for (int k0 = 0; k0 < K; k0 += 32) {
#pragma unroll
        for (int i = 0; i < 2; i++) {
            int r = lrA + i * 128;
            int so = r * ASTR + lcA;
            *(uint4*)(sAh + so) = *(const uint4*)(Ah + (size_t)(m0 + r) * K + k0 + lcA);
            *(uint4*)(sAl + so) = *(const uint4*)(Al + (size_t)(m0 + r) * K + k0 + lcA);
        }
        {
            int so = lrB * ASTR + lcB;
            *(uint4*)(sBh + so) = *(const uint4*)(Bh + (size_t)(n0 + lrB) * K + k0 + lcB);
            *(uint4*)(sBl + so) = *(const uint4*)(Bl + (size_t)(n0 + lrB) * K + k0 + lcB);
        }
        __syncthreads();

#pragma unroll
        for (int ks = 0; ks < 2; ks++) {
            uint32_t kbyte = (uint32_t)(ks * 16) * 2;
            uint32_t bh[2][4], bl[2][4];
#pragma unroll
            for (int np = 0; np < 2; np++) {
                uint32_t no = (uint32_t)(np * 16 * ASTR) * 2 + kbyte;
                LDM4(bh[np], baseBh + no);
                LDM4(bl[np], baseBl + no);
            }
#pragma unroll
            for (int mt = 0; mt < 4; mt++) {
                uint32_t mo = (uint32_t)(mt * 16 * ASTR) * 2 + kbyte;
                uint32_t ah[4], al[4];
                LDM4(ah, baseAh + mo);
                LDM4(al, baseAl + mo);
#pragma unroll
                for (int nt = 0; nt < 4; nt++) {
                    int np = nt >> 1, hs = (nt & 1) << 1;
                    uint32_t b0h = bh[np][hs], b1h = bh[np][hs + 1];
                    uint32_t b0l = bl[np][hs], b1l = bl[np][hs + 1];
                    mma16816(acc[mt][nt], ah[0], ah[1], ah[2], ah[3], b0h, b1h);
                    mma16816(acc[mt][nt], ah[0], ah[1], ah[2], ah[3], b0l, b1l);
                    mma16816(acc[mt][nt], al[0], al[1], al[2], al[3], b0h, b1h);
                }
            }
        }
        __syncthreads();
    }

#pragma unroll
    for (int mt = 0; mt < 4; mt++) {
#pragma unroll
        for (int nt = 0; nt < 4; nt++) {
            int row = m0 + warp_m + mt * 16 + gr;
            int col = n0 + warp_n + nt * 8 + 2 * q;
            *(float2*)(C + (size_t)row * N + col) = make_float2(acc[mt][nt][0], acc[mt][nt][1]);
            *(float2*)(C + (size_t)(row + 8) * N + col) = make_float2(acc[mt][nt][2], acc[mt][nt][3]);
        }
    }
}

// ---------------------------------------------------------------------------
// RoPE kernels (fp32, unchanged)
// ---------------------------------------------------------------------------
__global__ void rope_q_kernel(const float* __restrict__ cosb,
                              const float* __restrict__ sinb) {
    int idx = blockIdx.x * 256 + threadIdx.x;
    int i = idx & 31;
    int h = (idx >> 5) & (NH - 1);
    int s = idx >> 9;
    float c = cosb[s * RHALF + i];
    float sn = sinb[s * RHALF + i];
    float* p = g_q + ((size_t)s * NH + h) * HD;
    float x1 = p[i], x2 = p[i + RHALF];
    p[i] = x1 * c - x2 * sn;
    p[i + RHALF] = x1 * sn + x2 * c;
}

__global__ void rope_copy_k_v_kernel(const float* __restrict__ cosb,
                                     const float* __restrict__ sinb,
                                     float* __restrict__ out_k,
                                     float* __restrict__ out_v) {
    int idx = blockIdx.x * 256 + threadIdx.x;
    int t = idx & 127;
    int row = idx >> 7;
    int s = row >> 1;
    size_t base = (size_t)row * HD;
    float* kp = g_k + base;
    float* ok = out_k + base;

    if (t < 32) {
        float c = cosb[s * RHALF + t];
        float sn = sinb[s * RHALF + t];
        float x1 = kp[t], x2 = kp[t + RHALF];
        float r1 = x1 * c - x2 * sn;
        float r2 = x1 * sn + x2 * c;
        kp[t] = r1; kp[t + RHALF] = r2;
        ok[t] = r1; ok[t + RHALF] = r2;
    } else {
        int d = 64 + (t - 32) * 2;
        float2 x = *(const float2*)(kp + d);
        *(float2*)(ok + d) = x;
    }
    float2 v = *(const float2*)(g_v + base + t * 2);
    *(float2*)(out_v + base + t * 2) = v;
}

// ---------------------------------------------------------------------------
// Tensor-core flash attention (bf16x3), causal. BQ=64, BKEY=64.
// Fragment loads via ldmatrix.x4 (identical fragment values to the verified
// scalar path; halves fragment-load issue count).
// ---------------------------------------------------------------------------
#define QKS   264
#define VTS2  72
#define PSTR2 72
#define SSTR2 66

#define OFF_QH 0
#define OFF_QL 33792
#define OFF_KH 67584
#define OFF_KL 101376
#define OFF_VH 135168
#define OFF_VL 172032
#define OFF_PS 208896
#define OFF_ST 227328
#define ATT_SMEM 228096

__global__ void __launch_bounds__(256, 1) attn_mma(float scale) {
    extern __shared__ char smc[];
    __nv_bfloat16* sQh = (__nv_bfloat16*)(smc + OFF_QH);
    __nv_bfloat16* sQl = (__nv_bfloat16*)(smc + OFF_QL);
    __nv_bfloat16* sKh = (__nv_bfloat16*)(smc + OFF_KH);
    __nv_bfloat16* sKl = (__nv_bfloat16*)(smc + OFF_KL);
    __nv_bfloat16* sVh = (__nv_bfloat16*)(smc + OFF_VH);
    __nv_bfloat16* sVl = (__nv_bfloat16*)(smc + OFF_VL);
    float* sS = (float*)(smc + OFF_PS);              // unioned with Ph/Pl
    __nv_bfloat16* sPh = (__nv_bfloat16*)(smc + OFF_PS);
    __nv_bfloat16* sPl = sPh + 64 * PSTR2;
    float* mrow = (float*)(smc + OFF_ST);
    float* lrow = mrow + 64;
    float* arow = lrow + 64;

    int qb = gridDim.x - 1 - blockIdx.x;    // heavy causal tiles first
    int h = blockIdx.y, kvh = h / GQ;
    int tid = threadIdx.x, wid = tid >> 5, lane = tid & 31;
    int gr = lane >> 2, q = lane & 3;
    int mt = wid >> 1;
    int nh = wid & 1;
    int row0 = mt * 16 + gr;

    uint32_t aoffQ = (uint32_t)((mt * 16 + (lane & 15)) * QKS + ((lane >> 4) << 3)) * 2;
    uint32_t boffK = (uint32_t)((nh * 32 + (lane & 7) + ((lane >> 4) << 3)) * QKS
                                + (((lane >> 3) & 1) << 3)) * 2;
    uint32_t aoffP = (uint32_t)((mt * 16 + (lane & 15)) * PSTR2 + ((lane >> 4) << 3)) * 2;
    uint32_t boffV = (uint32_t)((nh * 128 + (lane & 7) + ((lane >> 4) << 3)) * VTS2
                                + (((lane >> 3) & 1) << 3)) * 2;

    uint32_t baseQh = smem_u32(sQh) + aoffQ;
    uint32_t baseQl = smem_u32(sQl) + aoffQ;
    uint32_t baseKh = smem_u32(sKh) + boffK;
    uint32_t baseKl = smem_u32(sKl) + boffK;
    uint32_t basePh = smem_u32(sPh) + aoffP;
    uint32_t basePl = smem_u32(sPl) + aoffP;
    uint32_t baseVh = smem_u32(sVh) + boffV;
    uint32_t baseVl = smem_u32(sVl) + boffV;

    for (int t = tid; t < 2048; t += 256) {
        int r = t >> 5, c = (t & 31) << 3;
        size_t g = ((size_t)(qb * 64 + r) * NH + h) * HD + c;
        *(uint4*)(sQh + r * QKS + c) = *(const uint4*)(g_qh + g);
        *(uint4*)(sQl + r * QKS + c) = *(const uint4*)(g_ql + g);
    }
    if (tid < 64) { mrow[tid] = -1e30f; lrow[tid] = 0.f; }

    float o[16][4];
#pragma unroll
    for (int nt = 0; nt < 16; nt++)
#pragma unroll
        for (int r = 0; r < 4; r++) o[nt][r] = 0.f;

    int nkb = qb + 1;
    for (int kb = 0; kb < nkb; kb++) {
        __syncthreads();
        for (int t = tid; t < 2048; t += 256) {
            int r = t >> 5, c = (t & 31) << 3;
            size_t g = ((size_t)(kb * 64 + r) * NKV + kvh) * HD + c;
            *(uint4*)(sKh + r * QKS + c) = *(const uint4*)(g_kh + g);
            *(uint4*)(sKl + r * QKS + c) = *(const uint4*)(g_kl + g);
        }
        for (int t = tid; t < 2048; t += 256) {
            int r = t >> 3, c = (t & 7) << 3;
            size_t g = ((size_t)kvh * HD + r) * SEQ + kb * 64 + c;
            *(uint4*)(sVh + r * VTS2 + c) = *(const uint4*)(g_vth + g);
            *(uint4*)(sVl + r * VTS2 + c) = *(const uint4*)(g_vtl + g);
        }
        __syncthreads();

        // ---- S = Q K^T (m16 x n32 per warp), bf16x3, ldmatrix ----
        float sacc[4][4];
#pragma unroll
        for (int nt = 0; nt < 4; nt++)
#pragma unroll
            for (int r = 0; r < 4; r++) sacc[nt][r] = 0.f;

#pragma unroll 4
        for (int ks = 0; ks < 16; ks++) {
            uint32_t kby = (uint32_t)ks * 32;   // 16 bf16 * 2B
            uint32_t qh4[4], ql4[4];
            LDM4(qh4, baseQh + kby);
            LDM4(ql4, baseQl + kby);
            uint32_t kh4[2][4], kl4[2][4];
#pragma unroll
            for (int np = 0; np < 2; np++) {
                uint32_t no = (uint32_t)(np * 16 * QKS) * 2 + kby;
                LDM4(kh4[np], baseKh + no);
                LDM4(kl4[np], baseKl + no);
            }
#pragma unroll
            for (int nt = 0; nt < 4; nt++) {
                int np = nt >> 1, hs = (nt & 1) << 1;
                uint32_t b0h = kh4[np][hs], b1h = kh4[np][hs + 1];
                uint32_t b0l = kl4[np][hs], b1l = kl4[np][hs + 1];
                mma16816(sacc[nt], qh4[0], qh4[1], qh4[2], qh4[3], b0h, b1h);
                mma16816(sacc[nt], qh4[0], qh4[1], qh4[2], qh4[3], b0l, b1l);
                mma16816(sacc[nt], ql4[0], ql4[1], ql4[2], ql4[3], b0h, b1h);
            }
        }
        int rg0 = qb * 64 + row0, rg1 = rg0 + 8;
#pragma unroll
        for (int nt = 0; nt < 4; nt++) {
            int cl = nh * 32 + nt * 8 + 2 * q;
            int cg = kb * 64 + cl;
            sS[row0 * SSTR2 + cl]           = (cg     <= rg0) ? sacc[nt][0] * scale : -1e30f;
            sS[row0 * SSTR2 + cl + 1]       = (cg + 1 <= rg0) ? sacc[nt][1] * scale : -1e30f;
            sS[(row0 + 8) * SSTR2 + cl]     = (cg     <= rg1) ? sacc[nt][2] * scale : -1e30f;
            sS[(row0 + 8) * SSTR2 + cl + 1] = (cg + 1 <= rg1) ? sacc[nt][3] * scale : -1e30f;
        }
        __syncthreads();

        // ---- online softmax: 4 threads per row ----
        int srow = tid >> 2, sub = tid & 3;
        float sv[16];
        float mx = -1e30f;
#pragma unroll
        for (int j = 0; j < 16; j++) {
            sv[j] = sS[srow * SSTR2 + sub * 16 + j];
            mx = fmaxf(mx, sv[j]);
        }
        mx = fmaxf(mx, __shfl_xor_sync(0xffffffffu, mx, 1));
        mx = fmaxf(mx, __shfl_xor_sync(0xffffffffu, mx, 2));
        float m_old = mrow[srow];
        float mnew = fmaxf(m_old, mx);
        float al = __expf(m_old - mnew);
        float lsum = 0.f;
#pragma unroll
        for (int j = 0; j < 16; j++) {
            sv[j] = __expf(sv[j] - mnew);
            lsum += sv[j];
        }
        lsum += __shfl_xor_sync(0xffffffffu, lsum, 1);
        lsum += __shfl_xor_sync(0xffffffffu, lsum, 2);
        if (sub == 0) {
            mrow[srow] = mnew;
            arow[srow] = al;
            lrow[srow] = lrow[srow] * al + lsum;
        }
        __syncthreads();

#pragma unroll
        for (int j = 0; j < 16; j += 2) {
            float p0 = sv[j], p1 = sv[j + 1];
            __nv_bfloat16 h0 = __float2bfloat16(p0);
            __nv_bfloat16 h1 = __float2bfloat16(p1);
            *(uint32_t*)(sPh + srow * PSTR2 + sub * 16 + j) = pack2bf16(p0, p1);
            *(uint32_t*)(sPl + srow * PSTR2 + sub * 16 + j) =
                pack2bf16(p0 - __bfloat162float(h0), p1 - __bfloat162float(h1));
        }

        float a0 = arow[row0], a1 = arow[row0 + 8];
#pragma unroll
        for (int nt = 0; nt < 16; nt++) {
            o[nt][0] *= a0; o[nt][1] *= a0;
            o[nt][2] *= a1; o[nt][3] *= a1;
        }
        __syncthreads();

        // ---- O += P @ V (m16 x n128 per warp), bf16x3, ldmatrix ----
#pragma unroll
        for (int ks = 0; ks < 4; ks++) {
            uint32_t kby = (uint32_t)ks * 32;
            uint32_t ph4[4], pl4[4];
            LDM4(ph4, basePh + kby);
            LDM4(pl4, basePl + kby);
#pragma unroll
            for (int np = 0; np < 8; np++) {
                uint32_t no = (uint32_t)(np * 16 * VTS2) * 2 + kby;
                uint32_t vh4[4], vl4[4];
                LDM4(vh4, baseVh + no);
                LDM4(vl4, baseVl + no);
#pragma unroll
                for (int h2 = 0; h2 < 2; h2++) {
                    int nt = np * 2 + h2, hs = h2 << 1;
                    uint32_t b0h = vh4[hs], b1h = vh4[hs + 1];
                    uint32_t b0l = vl4[hs], b1l = vl4[hs + 1];
                    mma16816(o[nt], ph4[0], ph4[1], ph4[2], ph4[3], b0h, b1h);
                    mma16816(o[nt], ph4[0], ph4[1], ph4[2], ph4[3], b0l, b1l);
                    mma16816(o[nt], pl4[0], pl4[1], pl4[2], pl4[3], b0h, b1h);
                }
            }
        }
    }

    __syncthreads();
    float li0 = 1.f / lrow[row0], li1 = 1.f / lrow[row0 + 8];
#pragma unroll
    for (int nt = 0; nt < 16; nt++) {
        int col = nh * 128 + nt * 8 + 2 * q;
        size_t b0 = ((size_t)(qb * 64 + row0) * NH + h) * HD + col;
        size_t b1 = ((size_t)(qb * 64 + row0 + 8) * NH + h) * HD + col;
        float v0 = o[nt][0] * li0, v1 = o[nt][1] * li0;
        float v2 = o[nt][2] * li1, v3 = o[nt][3] * li1;
        __nv_bfloat16 h0 = __float2bfloat16(v0), h1 = __float2bfloat16(v1);
        __nv_bfloat16 h2 = __float2bfloat16(v2), h3 = __float2bfloat16(v3);
        *(uint32_t*)(g_ctxh + b0) = pack2bf16(v0, v1);
        *(uint32_t*)(g_ctxh + b1) = pack2bf16(v2, v3);
        *(uint32_t*)(g_ctxl + b0) = pack2bf16(v0 - __bfloat162float(h0), v1 - __bfloat162float(h1));
        *(uint32_t*)(g_ctxl + b1) = pack2bf16(v2 - __bfloat162float(h2), v3 - __bfloat162float(h3));
    }
}

// ---------------------------------------------------------------------------
// Launch. Launch index 3 = gemm_mma_big(wq) — keeps the fixed ncu window on
// the dominant GEMM.
// ---------------------------------------------------------------------------
extern "C" void kernel_launch(void* const* d_in, const int* in_sizes, int n_in,
                              void* d_out, int out_size) {
    const float* hs   = (const float*)d_in[0];
    const float* cosb = (const float*)d_in[1];
    const float* sinb = (const float*)d_in[2];
    // d_in[3] = attention_mask (pure causal, applied analytically)
    const float* wq = (const float*)d_in[4];
    const float* wk = (const float*)d_in[5];
    const float* wv = (const float*)d_in[6];
    const float* wo = (const float*)d_in[7];

    float* out   = (float*)d_out;
    float* out_o = out;
    float* out_k = out + (size_t)SEQ * HIDDEN;
    float* out_v = out_k + (size_t)SEQ * NKV * HD;

    float *qp, *kp, *vp;
    cudaGetSymbolAddress((void**)&qp, g_q);
    cudaGetSymbolAddress((void**)&kp, g_k);
    cudaGetSymbolAddress((void**)&vp, g_v);
    __nv_bfloat16 *hsh, *hsl, *qh, *ql, *kh, *kl, *ctxh, *ctxl;
    __nv_bfloat16 *wqth, *wqtl, *wkth, *wktl, *wvth, *wvtl, *woth, *wotl;
    cudaGetSymbolAddress((void**)&hsh, g_hsh);   cudaGetSymbolAddress((void**)&hsl, g_hsl);
    cudaGetSymbolAddress((void**)&qh, g_qh);     cudaGetSymbolAddress((void**)&ql, g_ql);
    cudaGetSymbolAddress((void**)&kh, g_kh);     cudaGetSymbolAddress((void**)&kl, g_kl);
    cudaGetSymbolAddress((void**)&ctxh, g_ctxh); cudaGetSymbolAddress((void**)&ctxl, g_ctxl);
    cudaGetSymbolAddress((void**)&wqth, g_wqth); cudaGetSymbolAddress((void**)&wqtl, g_wqtl);
    cudaGetSymbolAddress((void**)&wkth, g_wkth); cudaGetSymbolAddress((void**)&wktl, g_wktl);
    cudaGetSymbolAddress((void**)&wvth, g_wvth); cudaGetSymbolAddress((void**)&wvtl, g_wvtl);
    cudaGetSymbolAddress((void**)&woth, g_woth); cudaGetSymbolAddress((void**)&wotl, g_wotl);

    cudaFuncSetAttribute(gemm_mma_big, cudaFuncAttributeMaxDynamicSharedMemorySize, GSMB);
    cudaFuncSetAttribute(attn_mma, cudaFuncAttributeMaxDynamicSharedMemorySize, ATT_SMEM);

    // 0: split activations
    split_hi_lo<<<(SEQ * HIDDEN / 4) / 256, 256>>>(hs, hsh, hsl);
    // 1-2: transposes needed before the profiled gemm
    transpose_split<<<dim3((NH * HD) / 32, HIDDEN / 32), 256>>>(wq, wqth, wqtl, HIDDEN, NH * HD);
    transpose_split<<<dim3((NKV * HD) / 32, HIDDEN / 32), 256>>>(wk, wkth, wktl, HIDDEN, NKV * HD);
    // 3: Q projection (256x128 tile) — the launch the ncu window captures
    gemm_mma_big<<<dim3((NH * HD) / 128, SEQ / 256), 512, GSMB>>>(hsh, hsl, wqth, wqtl, qp, SEQ, NH * HD, HIDDEN);
    // remaining prep + projections
    transpose_split<<<dim3((NKV * HD) / 32, HIDDEN / 32), 256>>>(wv, wvth, wvtl, HIDDEN, NKV * HD);
    transpose_split<<<dim3(HIDDEN / 32, (NH * HD) / 32), 256>>>(wo, woth, wotl, NH * HD, HIDDEN);
    gemm_mma<<<dim3((NKV * HD) / 128, SEQ / 128), 512>>>(hsh, hsl, wkth, wktl, kp, SEQ, NKV * HD, HIDDEN);
    gemm_mma<<<dim3((NKV * HD) / 128, SEQ / 128), 512>>>(hsh, hsl, wvth, wvtl, vp, SEQ, NKV * HD, HIDDEN);

    // RoPE on Q; fused RoPE+copy for K, copy for V
    rope_q_kernel<<<(SEQ * NH * RHALF) / 256, 256>>>(cosb, sinb);
    rope_copy_k_v_kernel<<<(SEQ * NKV * 128) / 256, 256>>>(cosb, sinb, out_k, out_v);

    // hi/lo splits for attention operands
    split_hi_lo<<<((size_t)SEQ * NH * HD / 4) / 256, 256>>>(qp, qh, ql);
    split_hi_lo<<<((size_t)SEQ * NKV * HD / 4) / 256, 256>>>(kp, kh, kl);
    vt_split<<<dim3(SEQ / 32, HD / 32, NKV), 256>>>();

    // Tensor-core flash attention (writes ctx hi/lo directly)
    attn_mma<<<dim3(SEQ / 64, NH), 256, ATT_SMEM>>>(0.0625f);  // 256^-0.5

    // Output projection (256x128 tile)
    gemm_mma_big<<<dim3(HIDDEN / 128, SEQ / 256), 512, GSMB>>>(ctxh, ctxl, woth, wotl, out_o, SEQ, HIDDEN, NH * HD);
}